// round 13
// baseline (speedup 1.0000x reference)
#include <cuda_runtime.h>
#include <cuda_bf16.h>
#include <math.h>
#include <stdint.h>

// Problem constants
#define BB 2
#define CC 64
#define DD 8
#define HH 128
#define WW 128
#define VV (DD*HH*WW)          // 131072
#define LL 101
#define KD 64
#define NLM 20
#define NN (100 + NLM)         // 120
#define EPSV 1e-3f

#define X_ELEMS   (BB*CC*VV)          // 16777216
#define IF_ELEMS  (BB*NN*CC)
#define PM_ELEMS  (BB*NN*VV)
#define PK_ELEMS  (BB*NN*KD)
#define OUT_FULL  (X_ELEMS + IF_ELEMS + PM_ELEMS + PK_ELEMS)

#define HALF_ELEMS 16777216           // bf16 elems per (hi|lo) half of a scratch buffer

// ---------------- device scratch ----------------
__device__ float g_bufA[X_ELEMS];     // Hi bf16 [0..16M) + Lo bf16 [16M..32M)
__device__ float g_bufB[X_ELEMS];
__device__ uint4 g_wfragHi[4*9*4*4*32];   // Whi in mma-A fragment order
__device__ uint4 g_wfragLo[4*9*4*4*32];   // Wlo in mma-A fragment order
__device__ uint4 g_kfrag[4096];           // knorm frags: [b][sv][kc][cogrp][lane]
__device__ float g_sums[BB*LL*CC];
__device__ float g_counts[BB*LL];
__device__ float g_kraw[BB*NN*KD];
__device__ float g_knorm[BB*NN*KD];
__device__ float g_gram[BB*64*64];
__device__ float g_msum[BB*64];
__device__ float g_scaleS;
__device__ float g_shiftS;

// ================= helpers =================
typedef unsigned long long u64t;
__device__ __forceinline__ uint32_t smem_u32(const void* p) {
    uint32_t a;
    asm("{ .reg .u64 t; cvta.to.shared.u64 t, %1; cvt.u32.u64 %0, t; }"
        : "=r"(a) : "l"(p));
    return a;
}
__device__ __forceinline__ uint32_t pack_bits(__nv_bfloat16 lo, __nv_bfloat16 hi) {
    return (uint32_t)__bfloat16_as_ushort(lo) | ((uint32_t)__bfloat16_as_ushort(hi) << 16);
}
__device__ __forceinline__ uint32_t pack_cvt(float lo, float hi) {
    uint32_t r;
    asm("cvt.rn.bf16x2.f32 %0, %1, %2;" : "=r"(r) : "f"(hi), "f"(lo));
    return r;
}
__device__ __forceinline__ float bf_round(float x) {
    return __bfloat162float(__float2bfloat16(x));
}

#define LDSM4(r0,r1,r2,r3, addr) \
    asm volatile("ldmatrix.sync.aligned.m8n8.x4.shared.b16 {%0,%1,%2,%3}, [%4];" \
        : "=r"(r0),"=r"(r1),"=r"(r2),"=r"(r3) : "r"(addr))

#define MMA16816(d, a0,a1,a2,a3, b0,b1) \
    asm volatile("mma.sync.aligned.m16n8k16.row.col.f32.bf16.bf16.f32 " \
        "{%0,%1,%2,%3}, {%4,%5,%6,%7}, {%8,%9}, {%0,%1,%2,%3};" \
        : "+f"((d)[0]), "+f"((d)[1]), "+f"((d)[2]), "+f"((d)[3]) \
        : "r"(a0),"r"(a1),"r"(a2),"r"(a3), "r"(b0),"r"(b1))

#define CP_ASYNC16(dst, src, n) \
    asm volatile("cp.async.cg.shared.global [%0], [%1], 16, %2;" \
        :: "r"(dst), "l"(src), "r"(n) : "memory")
#define CP_COMMIT() asm volatile("cp.async.commit_group;" ::: "memory")
#define CP_WAIT0()  asm volatile("cp.async.wait_group 0;" ::: "memory")
#define CP_WAIT1()  asm volatile("cp.async.wait_group 1;" ::: "memory")

// ---------------- init ----------------
__global__ void init_zero_kernel() {
    int tid = threadIdx.x;
    for (int i = tid; i < BB*LL*CC; i += 256) g_sums[i] = 0.f;
    for (int i = tid; i < BB*LL; i += 256) g_counts[i] = 0.f;
    for (int i = tid; i < BB*64*64; i += 256) g_gram[i] = 0.f;
    for (int i = tid; i < BB*64; i += 256) g_msum[i] = 0.f;
}

// ---------------- W -> mma A-fragment order, hi+lo tables (all 4 layers) ----------------
__global__ void wfrag_kernel(const float* __restrict__ w) {
    int idx = blockIdx.x * 256 + threadIdx.x;
    if (idx >= 18432) return;
    int lane = idx & 31;
    int r = idx >> 5;
    int cogrp = r & 3; r >>= 2;
    int kc = r & 3; r >>= 2;
    int tap = r % 9; int l = r / 9;
    int row = cogrp*16 + (lane >> 2);
    int c0 = kc*16 + (lane & 3)*2;
    float v[8];
    v[0] = w[((size_t)(l*64 + row)*64     + c0)*9 + tap];
    v[1] = w[((size_t)(l*64 + row)*64     + c0 + 1)*9 + tap];
    v[2] = w[((size_t)(l*64 + row + 8)*64 + c0)*9 + tap];
    v[3] = w[((size_t)(l*64 + row + 8)*64 + c0 + 1)*9 + tap];
    v[4] = w[((size_t)(l*64 + row)*64     + c0 + 8)*9 + tap];
    v[5] = w[((size_t)(l*64 + row)*64     + c0 + 9)*9 + tap];
    v[6] = w[((size_t)(l*64 + row + 8)*64 + c0 + 8)*9 + tap];
    v[7] = w[((size_t)(l*64 + row + 8)*64 + c0 + 9)*9 + tap];
    uint4 hi, lo;
    hi.x = pack_bits(__float2bfloat16(v[0]), __float2bfloat16(v[1]));
    hi.y = pack_bits(__float2bfloat16(v[2]), __float2bfloat16(v[3]));
    hi.z = pack_bits(__float2bfloat16(v[4]), __float2bfloat16(v[5]));
    hi.w = pack_bits(__float2bfloat16(v[6]), __float2bfloat16(v[7]));
    lo.x = pack_cvt(v[0] - bf_round(v[0]), v[1] - bf_round(v[1]));
    lo.y = pack_cvt(v[2] - bf_round(v[2]), v[3] - bf_round(v[3]));
    lo.z = pack_cvt(v[4] - bf_round(v[4]), v[5] - bf_round(v[5]));
    lo.w = pack_cvt(v[6] - bf_round(v[6]), v[7] - bf_round(v[7]));
    int off = ((l*9 + tap)*4 + kc)*128 + cogrp*32 + lane;
    g_wfragHi[off] = hi;
    g_wfragLo[off] = lo;
}

// ---------------- knorm -> mma A-fragment order, hi+lo (both batches) ----------------
__global__ void kfrag_kernel() {
    int idx = blockIdx.x * 256 + threadIdx.x;
    if (idx >= 4096) return;
    int lane = idx & 31;
    int r = idx >> 5;
    int cogrp = r & 7; r >>= 3;
    int kc = r & 3; r >>= 2;
    int sv = r & 1; int b = r >> 1;
    int row = cogrp*16 + (lane >> 2);
    int c0 = kc*16 + (lane & 3)*2;
    #define KV(rr, cc) ((rr) < NN ? g_knorm[((size_t)b*NN + (rr))*64 + (cc)] : 0.f)
    float v[8];
    v[0] = KV(row, c0);     v[1] = KV(row, c0+1);
    v[2] = KV(row+8, c0);   v[3] = KV(row+8, c0+1);
    v[4] = KV(row, c0+8);   v[5] = KV(row, c0+9);
    v[6] = KV(row+8, c0+8); v[7] = KV(row+8, c0+9);
    #undef KV
    uint4 o;
    if (sv == 0) {
        o.x = pack_bits(__float2bfloat16(v[0]), __float2bfloat16(v[1]));
        o.y = pack_bits(__float2bfloat16(v[2]), __float2bfloat16(v[3]));
        o.z = pack_bits(__float2bfloat16(v[4]), __float2bfloat16(v[5]));
        o.w = pack_bits(__float2bfloat16(v[6]), __float2bfloat16(v[7]));
    } else {
        o.x = pack_cvt(v[0] - bf_round(v[0]), v[1] - bf_round(v[1]));
        o.y = pack_cvt(v[2] - bf_round(v[2]), v[3] - bf_round(v[3]));
        o.z = pack_cvt(v[4] - bf_round(v[4]), v[5] - bf_round(v[5]));
        o.w = pack_cvt(v[6] - bf_round(v[6]), v[7] - bf_round(v[7]));
    }
    g_kfrag[((b*2 + sv)*4 + kc)*256 + cogrp*32 + lane] = o;
}

// ---------------- Gram: G[b] = MF MF^T (3-term bf16 split), msum[b] = sum_v MF_v ----
#define GCHUNK 2048
__global__ __launch_bounds__(256)
void gram_kernel(const float* __restrict__ mf) {
    __shared__ __align__(16) uint32_t sH[64*32];   // [ch][128B px bf16], swizzled
    __shared__ __align__(16) uint32_t sL[64*32];
    __shared__ float sMsum[64];
    const int b = blockIdx.y;
    const size_t vbase = (size_t)blockIdx.x * GCHUNK;
    const int tid = threadIdx.x, wid = tid >> 5, lane = tid & 31;
    const uint32_t sbH = smem_u32(sH), sbL = smem_u32(sL);
    if (tid < 64) sMsum[tid] = 0.f;

    const int mgrp = wid & 1;          // M32 group
    const int ngrp = wid >> 1;         // N16 group
    const int am  = (lane & 7) + ((lane >> 3) & 1) * 8;
    const int akh = lane >> 4;
    const int bn  = (lane & 7) + (lane >> 4) * 8;
    const int bkh = (lane >> 3) & 1;

    float acc[2][2][4] = {};
    const float* mfb = mf + (size_t)b*64*VV + vbase;

    for (int st = 0; st < GCHUNK/64; st++) {
        __syncthreads();
        const float* src = mfb + st*64;
        #pragma unroll
        for (int it = 0; it < 4; it++) {
            int i = tid + it*256;              // ch = i>>4, p4 = i&15
            int ch = i >> 4, p4 = i & 15;
            float4 v = *(const float4*)(src + (size_t)ch*VV + p4*4);
            __nv_bfloat16 h0 = __float2bfloat16(v.x);
            __nv_bfloat16 h1 = __float2bfloat16(v.y);
            __nv_bfloat16 h2 = __float2bfloat16(v.z);
            __nv_bfloat16 h3 = __float2bfloat16(v.w);
            uint32_t hA = pack_bits(h0, h1), hB = pack_bits(h2, h3);
            uint32_t lA = pack_cvt(v.x - __bfloat162float(h0), v.y - __bfloat162float(h1));
            uint32_t lB = pack_cvt(v.z - __bfloat162float(h2), v.w - __bfloat162float(h3));
            uint32_t off = (uint32_t)(ch*128 + ((((p4 >> 1) << 4) ^ ((ch & 7) << 4))) + (p4 & 1)*8);
            asm volatile("st.shared.v2.b32 [%0], {%1,%2};" :: "r"(sbH + off), "r"(hA), "r"(hB) : "memory");
            asm volatile("st.shared.v2.b32 [%0], {%1,%2};" :: "r"(sbL + off), "r"(lA), "r"(lB) : "memory");
            atomicAdd(&sMsum[ch], v.x + v.y + v.z + v.w);
        }
        __syncthreads();
        #pragma unroll
        for (int kc = 0; kc < 4; kc++) {
            const uint32_t ku  = (uint32_t)(kc*32 + akh*16);
            const uint32_t kub = (uint32_t)(kc*32 + bkh*16);
            const int r0 = mgrp*32 + am, r1 = r0 + 16;
            const uint32_t ax0 = (uint32_t)((r0 & 7) << 4);
            const int rB = ngrp*16 + bn;
            const uint32_t bx = (uint32_t)((rB & 7) << 4);
            uint32_t ah0,ah1,ah2,ah3, ag0,ag1,ag2,ag3;
            LDSM4(ah0,ah1,ah2,ah3, sbH + r0*128 + (ku ^ ax0));
            LDSM4(ag0,ag1,ag2,ag3, sbH + r1*128 + (ku ^ ax0));
            uint32_t al0,al1,al2,al3, am0,am1,am2,am3;
            LDSM4(al0,al1,al2,al3, sbL + r0*128 + (ku ^ ax0));
            LDSM4(am0,am1,am2,am3, sbL + r1*128 + (ku ^ ax0));
            uint32_t bh0,bh1,bh2,bh3, bl0,bl1,bl2,bl3;
            LDSM4(bh0,bh1,bh2,bh3, sbH + rB*128 + (kub ^ bx));
            LDSM4(bl0,bl1,bl2,bl3, sbL + rB*128 + (kub ^ bx));
            // hi*hi
            MMA16816(acc[0][0], ah0,ah1,ah2,ah3, bh0,bh1);
            MMA16816(acc[0][1], ah0,ah1,ah2,ah3, bh2,bh3);
            MMA16816(acc[1][0], ag0,ag1,ag2,ag3, bh0,bh1);
            MMA16816(acc[1][1], ag0,ag1,ag2,ag3, bh2,bh3);
            // hi*lo
            MMA16816(acc[0][0], ah0,ah1,ah2,ah3, bl0,bl1);
            MMA16816(acc[0][1], ah0,ah1,ah2,ah3, bl2,bl3);
            MMA16816(acc[1][0], ag0,ag1,ag2,ag3, bl0,bl1);
            MMA16816(acc[1][1], ag0,ag1,ag2,ag3, bl2,bl3);
            // lo*hi
            MMA16816(acc[0][0], al0,al1,al2,al3, bh0,bh1);
            MMA16816(acc[0][1], al0,al1,al2,al3, bh2,bh3);
            MMA16816(acc[1][0], am0,am1,am2,am3, bh0,bh1);
            MMA16816(acc[1][1], am0,am1,am2,am3, bh2,bh3);
        }
    }
    // write G partials
    #pragma unroll
    for (int mt = 0; mt < 2; mt++) {
        #pragma unroll
        for (int np = 0; np < 2; np++) {
            int row = mgrp*32 + mt*16 + (lane >> 2);
            int col = ngrp*16 + np*8 + 2*(lane & 3);
            float* Gp = g_gram + b*4096;
            atomicAdd(&Gp[row*64 + col],       acc[mt][np][0]);
            atomicAdd(&Gp[row*64 + col + 1],   acc[mt][np][1]);
            atomicAdd(&Gp[(row+8)*64 + col],   acc[mt][np][2]);
            atomicAdd(&Gp[(row+8)*64 + col+1], acc[mt][np][3]);
        }
    }
    __syncthreads();
    if (tid < 64) atomicAdd(&g_msum[b*64 + tid], sMsum[tid]);
}

// ---------------- analytic mask stats -> scale/shift ----------------
__global__ void stats_kernel(const float* __restrict__ gam, const float* __restrict__ bet) {
    __shared__ double sS[256], sQ[256];
    const int tid = threadIdx.x;
    double s = 0.0, q = 0.0;
    if (tid < BB*NN) {
        int b = tid / NN, n = tid % NN;
        const float* K = g_knorm + ((size_t)b*NN + n)*64;
        float kr[64];
        #pragma unroll
        for (int c = 0; c < 64; c++) kr[c] = K[c];
        const float* G = g_gram + b*4096;
        const float* M = g_msum + b*64;
        float qs = 0.f, ss = 0.f;
        #pragma unroll 4
        for (int c = 0; c < 64; c++) {
            float d = 0.f;
            #pragma unroll
            for (int e = 0; e < 64; e++) d = fmaf(G[c*64 + e], kr[e], d);
            qs = fmaf(kr[c], d, qs);
            ss = fmaf(kr[c], M[c], ss);
        }
        s = (double)ss; q = (double)qs;
    }
    sS[tid] = s; sQ[tid] = q;
    __syncthreads();
    for (int st = 128; st > 0; st >>= 1) {
        if (tid < st) { sS[tid] += sS[tid+st]; sQ[tid] += sQ[tid+st]; }
        __syncthreads();
    }
    if (tid == 0) {
        double mean = sS[0] / (double)PM_ELEMS;
        double ex2  = sQ[0] / (double)PM_ELEMS;
        double var  = ex2 - mean*mean;
        float inv = (float)(1.0 / sqrt(var + (double)EPSV));
        float sc = gam[0] * inv;
        g_scaleS = sc;
        g_shiftS = bet[0] - (float)mean * sc;
    }
}

// ---------------- features (ch-major fp32) -> pixel-major bf16 hi/lo ----------------
__global__ __launch_bounds__(256)
void trans_kernel(const float* __restrict__ in, uint16_t* __restrict__ outHi) {
    __shared__ float s[64][129];
    const int blk = blockIdx.x;
    const int sl = blk >> 7;
    const int h  = blk & 127;
    const int b = sl >> 3, d = sl & 7;
    const int tid = threadIdx.x;
    for (int i = tid; i < 8192; i += 256) {
        int c = i >> 7, w = i & 127;
        s[c][w] = in[((size_t)(b*64 + c)*8 + d)*16384 + h*128 + w];
    }
    __syncthreads();
    for (int i = tid; i < 1024; i += 256) {
        int w = i >> 3, ch = i & 7;
        uint32_t hw[4], lw[4];
        #pragma unroll
        for (int j = 0; j < 4; j++) {
            float v0 = s[ch*8 + 2*j][w];
            float v1 = s[ch*8 + 2*j + 1][w];
            __nv_bfloat16 h0 = __float2bfloat16(v0);
            __nv_bfloat16 h1 = __float2bfloat16(v1);
            hw[j] = pack_bits(h0, h1);
            lw[j] = pack_cvt(v0 - __bfloat162float(h0), v1 - __bfloat162float(h1));
        }
        size_t e = (((size_t)sl*128 + h)*128 + w)*64 + ch*8;
        *(uint4*)(outHi + e) = make_uint4(hw[0], hw[1], hw[2], hw[3]);
        *(uint4*)(outHi + HALF_ELEMS + e) = make_uint4(lw[0], lw[1], lw[2], lw[3]);
    }
}

// ================= mma.sync conv: 2 CTAs/SM, A from gmem fragment tables ==========
#define SM_IN    0            // 2 x 50688
#define SM_BIAS  101376
#define CONV_SMEM 101632
#define IN_ROW   8448         // 66 px * 128 B
#define BUF_STRIDE 50688
#define GRIDC 296

__global__ __launch_bounds__(256, 2)
void conv_mma_kernel(const uint16_t* __restrict__ inBuf,
                     void* __restrict__ outP,
                     const uint4* __restrict__ wfragHi,
                     const uint4* __restrict__ wfragLo,
                     const float* __restrict__ bias,
                     int mode)
{
    extern __shared__ char smem[];
    const uint32_t sb = smem_u32(smem);
    float* sBias = (float*)(smem + SM_BIAS);
    const int tid = threadIdx.x;
    const int wid = tid >> 5, lane = tid & 31;

    if (tid < 64) sBias[tid] = bias[tid];
    __syncthreads();

    const int ks      = wid >> 2;
    const int cg2     = (wid >> 1) & 1;
    const int co_base = cg2 * 32;
    const int px_base = (wid & 1) * 32;
    const int bn  = (lane & 7) + (lane >> 4) * 8;
    const int bkh = (lane >> 3) & 1;

    uint32_t meta[13];
    #pragma unroll
    for (int j = 0; j < 13; j++) {
        int i = tid + j*256;
        if (i < 3168) {
            int bsel = (i >= 1584) ? 1 : 0;
            int r = i - bsel*1584;
            int ky = r / 528; int rem = r - ky*528;
            int px = rem >> 3; int ch = rem & 7;
            uint32_t dsto = (uint32_t)(bsel*25344 + ky*IN_ROW + px*128 +
                                       ((ch ^ (px & 7)) << 4));
            meta[j] = dsto | ((uint32_t)ky << 16) | ((uint32_t)px << 18) |
                      ((uint32_t)ch << 25) | ((uint32_t)bsel << 28) | (1u << 31);
        } else meta[j] = 0;
    }

    auto stage_tile = [&](int buf, int t) {
        const int sl = t >> 8;
        const int h  = (t >> 1) & 127;
        const int w0 = (t & 1) << 6;
        const uint32_t dstBase = sb + SM_IN + buf*BUF_STRIDE;
        const uint16_t* base = inBuf + (size_t)sl * 1048576;
        #pragma unroll
        for (int j = 0; j < 13; j++) {
            uint32_t m = meta[j];
            if (m & (1u << 31)) {
                int ky = (m >> 16) & 3;
                int px = (m >> 18) & 127;
                int ch = (m >> 25) & 7;
                int bsel = (m >> 28) & 1;
                int gh = h + ky - 1, gw = w0 + px - 1;
                uint32_t ok = (((unsigned)gh < 128u) & ((unsigned)gw < 128u)) ? 1u : 0u;
                int cgh = ok ? gh : 0, cgw = ok ? gw : 0;
                const uint16_t* src = base + (size_t)bsel*HALF_ELEMS +
                        (((uint32_t)(cgh*128 + cgw)) << 6) + (ch << 3);
                CP_ASYNC16(dstBase + (m & 0xFFFFu), src, ok ? 16u : 0u);
            }
        }
        CP_COMMIT();
    };

    int t = blockIdx.x;
    int curbuf = 0;
    if (t < 4096) stage_tile(0, t);

    for (; t < 4096; t += GRIDC) {
        const int sl = t >> 8;
        const int h  = (t >> 1) & 127;
        const int w0 = (t & 1) << 6;
        const int nt = t + GRIDC;

        if (nt < 4096) { stage_tile(curbuf ^ 1, nt); CP_WAIT1(); }
        else           { CP_WAIT0(); }
        __syncthreads();

        const uint32_t inHi = sb + SM_IN + curbuf*BUF_STRIDE;
        const uint32_t inLo = inHi + 25344;

        float acc[2][4][4] = {};
        #pragma unroll
        for (int ky = 0; ky < 3; ky++) {
            const uint32_t bHrow = inHi + ky*IN_ROW;
            const uint32_t bLrow = inLo + ky*IN_ROW;
            #pragma unroll
            for (int kx = 0; kx < 3; kx++) {
                const int tap = ky*3 + kx;
                const int spx1 = px_base + bn + kx;
                const int spx2 = spx1 + 16;
                const uint32_t bH1 = bHrow + spx1*128;
                const uint32_t bH2 = bHrow + spx2*128;
                const uint32_t bL1 = bLrow + spx1*128;
                const uint32_t bL2 = bLrow + spx2*128;
                const uint32_t bx1 = (uint32_t)((spx1 & 7) << 4);
                const uint32_t bx2 = (uint32_t)((spx2 & 7) << 4);
                const uint4* whp = wfragHi + (tap*4)*128 + lane;
                const uint4* wlp = wfragLo + (tap*4)*128 + lane;
                #pragma unroll
                for (int kc2 = 0; kc2 < 2; kc2++) {
                    const int kc = ks*2 + kc2;
                    const uint32_t kub = (uint32_t)(kc*32 + bkh*16);
                    uint4 ah0 = whp[kc*128 + (2*cg2)*32];
                    uint4 ah1 = whp[kc*128 + (2*cg2 + 1)*32];
                    uint4 al0 = wlp[kc*128 + (2*cg2)*32];
                    uint4 al1 = wlp[kc*128 + (2*cg2 + 1)*32];
                    uint32_t h0,h1,h2,h3, h4,h5,h6,h7;
                    LDSM4(h0,h1,h2,h3, bH1 + (kub ^ bx1));
                    LDSM4(h4,h5,h6,h7, bH2 + (kub ^ bx2));
                    uint32_t l0,l1,l2,l3, l4,l5,l6,l7;
                    LDSM4(l0,l1,l2,l3, bL1 + (kub ^ bx1));
                    LDSM4(l4,l5,l6,l7, bL2 + (kub ^ bx2));
                    MMA16816(acc[0][0], ah0.x,ah0.y,ah0.z,ah0.w, h0,h1);
                    MMA16816(acc[0][1], ah0.x,ah0.y,ah0.z,ah0.w, h2,h3);
                    MMA16816(acc[0][2], ah0.x,ah0.y,ah0.z,ah0.w, h4,h5);
                    MMA16816(acc[0][3], ah0.x,ah0.y,ah0.z,ah0.w, h6,h7);
                    MMA16816(acc[0][0], ah0.x,ah0.y,ah0.z,ah0.w, l0,l1);
                    MMA16816(acc[0][1], ah0.x,ah0.y,ah0.z,ah0.w, l2,l3);
                    MMA16816(acc[0][2], ah0.x,ah0.y,ah0.z,ah0.w, l4,l5);
                    MMA16816(acc[0][3], ah0.x,ah0.y,ah0.z,ah0.w, l6,l7);
                    MMA16816(acc[0][0], al0.x,al0.y,al0.z,al0.w, h0,h1);
                    MMA16816(acc[0][1], al0.x,al0.y,al0.z,al0.w, h2,h3);
                    MMA16816(acc[0][2], al0.x,al0.y,al0.z,al0.w, h4,h5);
                    MMA16816(acc[0][3], al0.x,al0.y,al0.z,al0.w, h6,h7);
                    MMA16816(acc[1][0], ah1.x,ah1.y,ah1.z,ah1.w, h0,h1);
                    MMA16816(acc[1][1], ah1.x,ah1.y,ah1.z,ah1.w, h2,h3);
                    MMA16816(acc[1][2], ah1.x,ah1.y,ah1.z,ah1.w, h4,h5);
                    MMA16816(acc[1][3], ah1.x,ah1.y,ah1.z,ah1.w, h6,h7);
                    MMA16816(acc[1][0], ah1.x,ah1.y,ah1.z,ah1.w, l0,l1);
                    MMA16816(acc[1][1], ah1.x,ah1.y,ah1.z,ah1.w, l2,l3);
                    MMA16816(acc[1][2], ah1.x,ah1.y,ah1.z,ah1.w, l4,l5);
                    MMA16816(acc[1][3], ah1.x,ah1.y,ah1.z,ah1.w, l6,l7);
                    MMA16816(acc[1][0], al1.x,al1.y,al1.z,al1.w, h0,h1);
                    MMA16816(acc[1][1], al1.x,al1.y,al1.z,al1.w, h2,h3);
                    MMA16816(acc[1][2], al1.x,al1.y,al1.z,al1.w, h4,h5);
                    MMA16816(acc[1][3], al1.x,al1.y,al1.z,al1.w, h6,h7);
                }
            }
        }
        __syncthreads();

        float* Sbase = (float*)(smem + SM_IN + curbuf*BUF_STRIDE);
        float* Sw = Sbase + ks*4160;
        #pragma unroll
        for (int mt = 0; mt < 2; mt++) {
            #pragma unroll
            for (int j = 0; j < 4; j++) {
                int pc = px_base + 8*j + 2*(lane & 3);
                int mr = co_base + mt*16 + (lane >> 2);
                Sw[pc*65 + mr]           = acc[mt][j][0];
                Sw[(pc+1)*65 + mr]       = acc[mt][j][1];
                Sw[pc*65 + mr + 8]       = acc[mt][j][2];
                Sw[(pc+1)*65 + mr + 8]   = acc[mt][j][3];
            }
        }
        __syncthreads();

        const float* S0 = Sbase;
        const float* S1 = Sbase + 4160;
        if (mode == 0) {
            const int px = tid >> 2, cb = (tid & 3) * 16;
            uint32_t hw[8], lw[8];
            #pragma unroll
            for (int j = 0; j < 8; j++) {
                int i0 = px*65 + cb + 2*j;
                float v0 = fmaxf(S0[i0]     + S1[i0]     + sBias[cb + 2*j],     0.f);
                float v1 = fmaxf(S0[i0 + 1] + S1[i0 + 1] + sBias[cb + 2*j + 1], 0.f);
                __nv_bfloat16 h0 = __float2bfloat16(v0);
                __nv_bfloat16 h1 = __float2bfloat16(v1);
                hw[j] = pack_bits(h0, h1);
                lw[j] = pack_cvt(v0 - __bfloat162float(h0), v1 - __bfloat162float(h1));
            }
            uint16_t* ob = (uint16_t*)outP;
            size_t e = (((size_t)sl*128 + h)*128 + (w0 + px))*64 + cb;
            *(uint4*)(ob + e)     = make_uint4(hw[0], hw[1], hw[2], hw[3]);
            *(uint4*)(ob + e + 8) = make_uint4(hw[4], hw[5], hw[6], hw[7]);
            *(uint4*)(ob + HALF_ELEMS + e)     = make_uint4(lw[0], lw[1], lw[2], lw[3]);
            *(uint4*)(ob + HALF_ELEMS + e + 8) = make_uint4(lw[4], lw[5], lw[6], lw[7]);
        } else {
            const int co = tid >> 2, pb = (tid & 3) * 16;
            const int b_ = sl >> 3, d_ = sl & 7;
            const float bv = sBias[co];
            float* ob = (float*)outP +
                ((size_t)(b_*64 + co)*8 + d_)*16384 + h*128 + w0 + pb;
            #pragma unroll
            for (int q = 0; q < 4; q++) {
                float4 o;
                int i0 = (pb + 4*q)*65 + co;
                o.x = fmaxf(S0[i0]        + S1[i0]        + bv, 0.f);
                o.y = fmaxf(S0[i0 + 65]   + S1[i0 + 65]   + bv, 0.f);
                o.z = fmaxf(S0[i0 + 130]  + S1[i0 + 130]  + bv, 0.f);
                o.w = fmaxf(S0[i0 + 195]  + S1[i0 + 195]  + bv, 0.f);
                *(float4*)(ob + 4*q) = o;
            }
        }
        __syncthreads();
        curbuf ^= 1;
    }
}

// ---------------- segment sums ----------------
#define VCH 2048
__global__ __launch_bounds__(256)
void segsum_kernel(const float* __restrict__ x, const int* __restrict__ labels)
{
    __shared__ float sAcc[LL*CC];
    __shared__ float sCnt[LL];
    __shared__ int sLab[VCH];
    const int b = blockIdx.y;
    const int v0 = blockIdx.x * VCH;
    const int tid = threadIdx.x;

    for (int i = tid; i < LL*CC; i += 256) sAcc[i] = 0.f;
    for (int i = tid; i < LL; i += 256) sCnt[i] = 0.f;
    for (int i = tid; i < VCH; i += 256) sLab[i] = labels[(size_t)b*VV + v0 + i];
    __syncthreads();

    for (int i = tid; i < VCH; i += 256) atomicAdd(&sCnt[sLab[i]], 1.f);
    const float* xb = x + (size_t)b*64*VV + v0;
    for (int c = 0; c < 64; c++) {
        const float* xc = xb + (size_t)c*VV;
        for (int i = tid; i < VCH; i += 256)
            atomicAdd(&sAcc[sLab[i]*64 + c], xc[i]);
    }
    __syncthreads();
    for (int i = tid; i < LL*CC; i += 256) atomicAdd(&g_sums[b*LL*CC + i], sAcc[i]);
    for (int i = tid; i < LL; i += 256) atomicAdd(&g_counts[b*LL + i], sCnt[i]);
}

// ---------------- inst features + mask_kernel linear ----------------
__global__ __launch_bounds__(256)
void instfeat_kernel(const float* __restrict__ embed, const float* __restrict__ mk_w,
                     const float* __restrict__ mk_b, float* __restrict__ if_out,
                     int write_if)
{
    __shared__ float sInst[NN*CC];
    __shared__ float sWT[CC*KD];
    const int b = blockIdx.x;
    const int tid = threadIdx.x;

    for (int idx = tid; idx < CC*KD; idx += 256) {
        int kd = idx & 63, c = idx >> 6;
        sWT[c*64 + kd] = mk_w[kd*64 + c];
    }
    for (int idx = tid; idx < 100*CC; idx += 256) {
        int n = idx >> 6, c = idx & 63;
        int l = n + 1;
        float cnt = fmaxf(g_counts[b*LL + l], 1.f);
        sInst[idx] = g_sums[(b*LL + l)*64 + c] / cnt;
    }
    for (int idx = tid; idx < NLM*CC; idx += 256)
        sInst[100*CC + idx] = embed[idx];
    __syncthreads();

    if (write_if)
        for (int idx = tid; idx < NN*CC; idx += 256)
            if_out[(size_t)b*NN*CC + idx] = sInst[idx];

    for (int idx = tid; idx < NN*KD; idx += 256) {
        int n = idx >> 6, kd = idx & 63;
        const float* ip = sInst + n*64;
        float a = mk_b[kd];
        #pragma unroll
        for (int c = 0; c < 64; c++)
            a = fmaf(ip[c], sWT[c*64 + kd], a);
        g_kraw[(size_t)b*NN*KD + idx] = a;
    }
}

// ---------------- BatchNorm1d over (B,N) per KD channel (parallel) ----------------
__global__ __launch_bounds__(256)
void bnk_kernel(const float* __restrict__ gamma, const float* __restrict__ beta,
                float* __restrict__ pk_out, int write_pk)
{
    __shared__ float ssum[256], ssq[256];
    __shared__ float sm[64], si[64], sg[64], sbt[64];
    const int tid = threadIdx.x;
    const int kd = tid & 63, q = tid >> 6;
    float s = 0.f, sq = 0.f;
    for (int i = q; i < BB*NN; i += 4) {
        float v = g_kraw[i*64 + kd];
        s += v; sq += v*v;
    }
    ssum[tid] = s; ssq[tid] = sq;
    __syncthreads();
    if (tid < 64) {
        float S = ssum[tid] + ssum[tid+64] + ssum[tid+128] + ssum[tid+192];
        float Q = ssq[tid] + ssq[tid+64] + ssq[tid+128] + ssq[tid+192];
        float mean = S / (float)(BB*NN);
        float var = Q / (float)(BB*NN) - mean*mean;
        sm[tid] = mean;
        si[tid] = rsqrtf(var + EPSV);
        sg[tid] = gamma[tid];
        sbt[tid] = beta[tid];
    }
    __syncthreads();
    for (int e = tid; e < BB*NN*KD; e += 256) {
        int k2 = e & 63;
        float v = (g_kraw[e] - sm[k2]) * si[k2] * sg[k2] + sbt[k2];
        g_knorm[e] = v;
        if (write_pk) pk_out[e] = v;
    }
}

// ---------------- bmm via mma.sync with fused normalization ----------------
#define BM_BH 0
#define BM_BL 8192
#define BM_S  16384
#define BMM_SMEM (16384 + 33280)      // 49664

__global__ __launch_bounds__(256)
void bmm_mma_kernel(const float* __restrict__ mf, float* __restrict__ pm)
{
    extern __shared__ char bsm[];
    const uint32_t sb = smem_u32(bsm);
    float* S = (float*)(bsm + BM_S);
    const int b = blockIdx.y;
    const int v0 = blockIdx.x * 64;
    const int tid = threadIdx.x;
    const int wid = tid >> 5, lane = tid & 31;

    {
        const float* mb = mf + ((size_t)(b*64 + 8*wid))*VV + v0;
        #pragma unroll
        for (int it = 0; it < 2; it++) {
            const int px = lane + it*32;
            float x[8];
            #pragma unroll
            for (int kk = 0; kk < 8; kk++)
                x[kk] = mb[(size_t)kk*VV + px];
            uint32_t hw[4], lw[4];
            #pragma unroll
            for (int j = 0; j < 4; j++) {
                float a = x[2*j], c = x[2*j + 1];
                __nv_bfloat16 ha = __float2bfloat16(a);
                __nv_bfloat16 hc = __float2bfloat16(c);
                hw[j] = pack_bits(ha, hc);
                lw[j] = pack_cvt(a - __bfloat162float(ha), c - __bfloat162float(hc));
            }
            uint32_t addr = (uint32_t)(px*128 + ((wid ^ (px & 7)) << 4));
            asm volatile("st.shared.v4.b32 [%0], {%1,%2,%3,%4};"
                :: "r"(sb + BM_BH + addr), "r"(hw[0]), "r"(hw[1]), "r"(hw[2]), "r"(hw[3]) : "memory");
            asm volatile("st.shared.v4.b32 [%0], {%1,%2,%3,%4};"
                :: "r"(sb + BM_BL + addr), "r"(lw[0]), "r"(lw[1]), "r"(lw[2]), "r"(lw[3]) : "memory");
        }
    }
    __syncthreads();

    const int mgrp = wid >> 1;
    const int pxg  = wid & 1;
    const int bn  = (lane & 7) + (lane >> 4) * 8;
    const int bkh = (lane >> 3) & 1;
    const int spx1 = pxg*32 + bn;
    const int spx2 = spx1 + 16;
    const uint32_t bH1 = sb + BM_BH + spx1*128;
    const uint32_t bH2 = sb + BM_BH + spx2*128;
    const uint32_t bL1 = sb + BM_BL + spx1*128;
    const uint32_t bL2 = sb + BM_BL + spx2*128;
    const uint32_t bx1 = (uint32_t)((spx1 & 7) << 4);
    const uint32_t bx2 = (uint32_t)((spx2 & 7) << 4);
    const uint4* khp = g_kfrag + (b*2 + 0)*1024;
    const uint4* klp = g_kfrag + (b*2 + 1)*1024;

    float acc[2][4][4] = {};
    #pragma unroll
    for (int kc = 0; kc < 4; kc++) {
        const uint32_t kub = (uint32_t)(kc*32 + bkh*16);
        uint4 ah0 = khp[kc*256 + (mgrp*2)*32 + lane];
        uint4 ah1 = khp[kc*256 + (mgrp*2 + 1)*32 + lane];
        uint4 al0 = klp[kc*256 + (mgrp*2)*32 + lane];
        uint4 al1 = klp[kc*256 + (mgrp*2 + 1)*32 + lane];
        uint32_t h0,h1,h2,h3, h4,h5,h6,h7;
        LDSM4(h0,h1,h2,h3, bH1 + (kub ^ bx1));
        LDSM4(h4,h5,h6,h7, bH2 + (kub ^ bx2));
        uint32_t l0,l1,l2,l3, l4,l5,l6,l7;
        LDSM4(l0,l1,l2,l3, bL1 + (kub ^ bx1));
        LDSM4(l4,l5,l6,l7, bL2 + (kub ^ bx2));
        MMA16816(acc[0][0], ah0.x,ah0.y,ah0.z,ah0.w, h0,h1);
        MMA16816(acc[0][1], ah0.x,ah0.y,ah0.z,ah0.w, h2,h3);
        MMA16816(acc[0][2], ah0.x,ah0.y,ah0.z,ah0.w, h4,h5);
        MMA16816(acc[0][3], ah0.x,ah0.y,ah0.z,ah0.w, h6,h7);
        MMA16816(acc[0][0], ah0.x,ah0.y,ah0.z,ah0.w, l0,l1);
        MMA16816(acc[0][1], ah0.x,ah0.y,ah0.z,ah0.w, l2,l3);
        MMA16816(acc[0][2], ah0.x,ah0.y,ah0.z,ah0.w, l4,l5);
        MMA16816(acc[0][3], ah0.x,ah0.y,ah0.z,ah0.w, l6,l7);
        MMA16816(acc[0][0], al0.x,al0.y,al0.z,al0.w, h0,h1);
        MMA16816(acc[0][1], al0.x,al0.y,al0.z,al0.w, h2,h3);
        MMA16816(acc[0][2], al0.x,al0.y,al0.z,al0.w, h4,h5);
        MMA16816(acc[0][3], al0.x,al0.y,al0.z,al0.w, h6,h7);
        MMA16816(acc[1][0], ah1.x,ah1.y,ah1.z,ah1.w, h0,h1);
        MMA16816(acc[1][1], ah1.x,ah1.y,ah1.z,ah1.w, h2,h3);
        MMA16816(acc[1][2], ah1.x,ah1.y,ah1.z,ah1.w, h4,h5);
        MMA16816(acc[1][3], ah1.x,ah1.y,ah1.z,ah1.w, h6,h7);
        MMA16816(acc[1][0], ah1.x,ah1.y,ah1.z,ah1.w, l0,l1);
        MMA16816(acc[1][1], ah1.x,ah1.y,ah1.z,ah1.w, l2,l3);
        MMA16816(acc[1][2], ah1.x,ah1.y,ah1.z,ah1.w, l4,l5);
        MMA16816(acc[1][3], ah1.x,ah1.y,ah1.z,ah1.w, l6,l7);
        MMA16816(acc[1][0], al1.x,al1.y,al1.z,al1.w, h0,h1);
        MMA16816(acc[1][1], al1.x,al1.y,al1.z,al1.w, h2,h3);
        MMA16816(acc[1][2], al1.x,al1.y,al1.z,al1.w, h4,h5);
        MMA16816(acc[1][3], al1.x,al1.y,al1.z,al1.w, h6,h7);
    }

    #pragma unroll
    for (int mt = 0; mt < 2; mt++) {
        #pragma unroll
        for (int j = 0; j < 4; j++) {
            int pc = pxg*32 + 8*j + 2*(lane & 3);
            int mr = mgrp*32 + mt*16 + (lane >> 2);
            S[mr*65 + pc]           = acc[mt][j][0];
            S[mr*65 + pc + 1]       = acc[mt][j][1];
            S[(mr+8)*65 + pc]       = acc[mt][j][2];
            S[(mr+8)*65 + pc + 1]   = acc[mt][j][3];
        }
    }
    __syncthreads();

    // write normalized masks
    const float sc = g_scaleS, sh = g_shiftS;
    float* po = pm + (size_t)b*NN*VV + v0;
    for (int idx = tid; idx < NN*64; idx += 256) {
        int n = idx >> 6, px = idx & 63;
        po[(size_t)n*VV + px] = S[n*65 + px] * sc + sh;
    }
}

// ---------------- launch ----------------
extern "C" void kernel_launch(void* const* d_in, const int* in_sizes, int n_in,
                              void* d_out, int out_size)
{
    const float* features      = (const float*)d_in[0];
    const float* mask_features = (const float*)d_in[1];
    const float* conv_w        = (const float*)d_in[2];
    const float* conv_b        = (const float*)d_in[3];
    const float* embed         = (const float*)d_in[4];
    const float* mk_w          = (const float*)d_in[5];
    const float* mk_b          = (const float*)d_in[6];
    const float* nk_gamma      = (const float*)d_in[7];
    const float* nk_beta       = (const float*)d_in[8];
    const float* nl_gamma      = (const float*)d_in[9];
    const float* nl_beta       = (const float*)d_in[10];
    const int*   init_masks    = (const int*)d_in[11];
    float* out = (float*)d_out;

    float *bufA = nullptr, *bufB = nullptr;
    uint4 *wfragHi = nullptr, *wfragLo = nullptr;
    cudaGetSymbolAddress((void**)&bufA, g_bufA);
    cudaGetSymbolAddress((void**)&bufB, g_bufB);
    cudaGetSymbolAddress((void**)&wfragHi, g_wfragHi);
    cudaGetSymbolAddress((void**)&wfragLo, g_wfragLo);
    uint16_t* hA = (uint16_t*)bufA;
    uint16_t* hB = (uint16_t*)bufB;

    int full = (out_size >= OUT_FULL) ? 1 : 0;
    int masks_only = (!full && out_size >= PM_ELEMS) ? 1 : 0;

    float* xout  = full ? out : bufB;
    float* ifout = full ? (out + X_ELEMS) : out;
    float* pmout = full ? (out + X_ELEMS + IF_ELEMS) : (masks_only ? out : bufB);
    float* pkout = full ? (out + X_ELEMS + IF_ELEMS + PM_ELEMS) : out;

    static int attr_done = 0;
    if (!attr_done) {
        cudaFuncSetAttribute(conv_mma_kernel,
                             cudaFuncAttributeMaxDynamicSharedMemorySize, CONV_SMEM);
        cudaFuncSetAttribute(bmm_mma_kernel,
                             cudaFuncAttributeMaxDynamicSharedMemorySize, BMM_SMEM);
        attr_done = 1;
    }

    init_zero_kernel<<<1, 256>>>();
    wfrag_kernel<<<72, 256>>>(conv_w);
    trans_kernel<<<2048, 256>>>(features, hB);

    conv_mma_kernel<<<GRIDC, 256, CONV_SMEM>>>(hB, hA,   wfragHi + 0*4608, wfragLo + 0*4608, conv_b + 0,   0);
    conv_mma_kernel<<<GRIDC, 256, CONV_SMEM>>>(hA, hB,   wfragHi + 1*4608, wfragLo + 1*4608, conv_b + 64,  0);
    conv_mma_kernel<<<GRIDC, 256, CONV_SMEM>>>(hB, hA,   wfragHi + 2*4608, wfragLo + 2*4608, conv_b + 128, 0);
    conv_mma_kernel<<<GRIDC, 256, CONV_SMEM>>>(hA, xout, wfragHi + 3*4608, wfragLo + 3*4608, conv_b + 192, 1);

    segsum_kernel<<<dim3(VV/VCH, BB), 256>>>(xout, init_masks);
    instfeat_kernel<<<BB, 256>>>(embed, mk_w, mk_b, ifout, full);
    bnk_kernel<<<1, 256>>>(nk_gamma, nk_beta, pkout, full);

    if (full || masks_only) {
        gram_kernel<<<dim3(VV/GCHUNK, BB), 256>>>(mask_features);
        kfrag_kernel<<<16, 256>>>();
        stats_kernel<<<1, 256>>>(nl_gamma, nl_beta);
        bmm_mma_kernel<<<dim3(VV/64, BB), 256, BMM_SMEM>>>(mask_features, pmout);
    }
}

// round 14
// speedup vs baseline: 1.0977x; 1.0977x over previous
#include <cuda_runtime.h>
#include <cuda_bf16.h>
#include <math.h>
#include <stdint.h>

// Problem constants
#define BB 2
#define CC 64
#define DD 8
#define HH 128
#define WW 128
#define VV (DD*HH*WW)          // 131072
#define LL 101
#define KD 64
#define NLM 20
#define NN (100 + NLM)         // 120
#define EPSV 1e-3f

#define X_ELEMS   (BB*CC*VV)          // 16777216
#define IF_ELEMS  (BB*NN*CC)
#define PM_ELEMS  (BB*NN*VV)
#define PK_ELEMS  (BB*NN*KD)
#define OUT_FULL  (X_ELEMS + IF_ELEMS + PM_ELEMS + PK_ELEMS)

#define HALF_ELEMS 16777216           // bf16 elems per (hi|lo) half of a scratch buffer

// ---------------- device scratch ----------------
__device__ float g_bufA[X_ELEMS];     // Hi bf16 [0..16M) + Lo bf16 [16M..32M)
__device__ float g_bufB[X_ELEMS];
__device__ uint4 g_wfragHi[4*9*4*4*32];   // Whi in mma-A fragment order
__device__ uint4 g_wfragLo[4*9*4*4*32];   // Wlo in mma-A fragment order
__device__ uint4 g_kfrag[4096];           // knorm frags: [b][sv][kc][cogrp][lane]
__device__ float g_sums[BB*LL*CC];
__device__ float g_counts[BB*LL];
__device__ float g_kraw[BB*NN*KD];
__device__ float g_knorm[BB*NN*KD];
__device__ float g_gram[BB*64*64];
__device__ float g_msum[BB*64];
__device__ float g_scaleS;
__device__ float g_shiftS;

// ================= helpers =================
typedef unsigned long long u64t;
__device__ __forceinline__ uint32_t smem_u32(const void* p) {
    uint32_t a;
    asm("{ .reg .u64 t; cvta.to.shared.u64 t, %1; cvt.u32.u64 %0, t; }"
        : "=r"(a) : "l"(p));
    return a;
}
__device__ __forceinline__ uint32_t pack_bits(__nv_bfloat16 lo, __nv_bfloat16 hi) {
    return (uint32_t)__bfloat16_as_ushort(lo) | ((uint32_t)__bfloat16_as_ushort(hi) << 16);
}
__device__ __forceinline__ uint32_t pack_cvt(float lo, float hi) {
    uint32_t r;
    asm("cvt.rn.bf16x2.f32 %0, %1, %2;" : "=r"(r) : "f"(hi), "f"(lo));
    return r;
}
__device__ __forceinline__ float bf_round(float x) {
    return __bfloat162float(__float2bfloat16(x));
}

#define LDSM4(r0,r1,r2,r3, addr) \
    asm volatile("ldmatrix.sync.aligned.m8n8.x4.shared.b16 {%0,%1,%2,%3}, [%4];" \
        : "=r"(r0),"=r"(r1),"=r"(r2),"=r"(r3) : "r"(addr))

#define MMA16816(d, a0,a1,a2,a3, b0,b1) \
    asm volatile("mma.sync.aligned.m16n8k16.row.col.f32.bf16.bf16.f32 " \
        "{%0,%1,%2,%3}, {%4,%5,%6,%7}, {%8,%9}, {%0,%1,%2,%3};" \
        : "+f"((d)[0]), "+f"((d)[1]), "+f"((d)[2]), "+f"((d)[3]) \
        : "r"(a0),"r"(a1),"r"(a2),"r"(a3), "r"(b0),"r"(b1))

#define CP_ASYNC16(dst, src, n) \
    asm volatile("cp.async.cg.shared.global [%0], [%1], 16, %2;" \
        :: "r"(dst), "l"(src), "r"(n) : "memory")
#define CP_COMMIT() asm volatile("cp.async.commit_group;" ::: "memory")
#define CP_WAIT0()  asm volatile("cp.async.wait_group 0;" ::: "memory")
#define CP_WAIT1()  asm volatile("cp.async.wait_group 1;" ::: "memory")

// ---------------- init ----------------
__global__ void init_zero_kernel() {
    int tid = threadIdx.x;
    for (int i = tid; i < BB*LL*CC; i += 256) g_sums[i] = 0.f;
    for (int i = tid; i < BB*LL; i += 256) g_counts[i] = 0.f;
    for (int i = tid; i < BB*64*64; i += 256) g_gram[i] = 0.f;
    for (int i = tid; i < BB*64; i += 256) g_msum[i] = 0.f;
}

// ---------------- W -> mma A-fragment order, hi+lo tables (all 4 layers) ----------------
__global__ void wfrag_kernel(const float* __restrict__ w) {
    int idx = blockIdx.x * 256 + threadIdx.x;
    if (idx >= 18432) return;
    int lane = idx & 31;
    int r = idx >> 5;
    int cogrp = r & 3; r >>= 2;
    int kc = r & 3; r >>= 2;
    int tap = r % 9; int l = r / 9;
    int row = cogrp*16 + (lane >> 2);
    int c0 = kc*16 + (lane & 3)*2;
    float v[8];
    v[0] = w[((size_t)(l*64 + row)*64     + c0)*9 + tap];
    v[1] = w[((size_t)(l*64 + row)*64     + c0 + 1)*9 + tap];
    v[2] = w[((size_t)(l*64 + row + 8)*64 + c0)*9 + tap];
    v[3] = w[((size_t)(l*64 + row + 8)*64 + c0 + 1)*9 + tap];
    v[4] = w[((size_t)(l*64 + row)*64     + c0 + 8)*9 + tap];
    v[5] = w[((size_t)(l*64 + row)*64     + c0 + 9)*9 + tap];
    v[6] = w[((size_t)(l*64 + row + 8)*64 + c0 + 8)*9 + tap];
    v[7] = w[((size_t)(l*64 + row + 8)*64 + c0 + 9)*9 + tap];
    uint4 hi, lo;
    hi.x = pack_bits(__float2bfloat16(v[0]), __float2bfloat16(v[1]));
    hi.y = pack_bits(__float2bfloat16(v[2]), __float2bfloat16(v[3]));
    hi.z = pack_bits(__float2bfloat16(v[4]), __float2bfloat16(v[5]));
    hi.w = pack_bits(__float2bfloat16(v[6]), __float2bfloat16(v[7]));
    lo.x = pack_cvt(v[0] - bf_round(v[0]), v[1] - bf_round(v[1]));
    lo.y = pack_cvt(v[2] - bf_round(v[2]), v[3] - bf_round(v[3]));
    lo.z = pack_cvt(v[4] - bf_round(v[4]), v[5] - bf_round(v[5]));
    lo.w = pack_cvt(v[6] - bf_round(v[6]), v[7] - bf_round(v[7]));
    int off = ((l*9 + tap)*4 + kc)*128 + cogrp*32 + lane;
    g_wfragHi[off] = hi;
    g_wfragLo[off] = lo;
}

// ---------------- knorm -> mma A-fragment order, hi+lo (both batches) ----------------
__global__ void kfrag_kernel() {
    int idx = blockIdx.x * 256 + threadIdx.x;
    if (idx >= 4096) return;
    int lane = idx & 31;
    int r = idx >> 5;
    int cogrp = r & 7; r >>= 3;
    int kc = r & 3; r >>= 2;
    int sv = r & 1; int b = r >> 1;
    int row = cogrp*16 + (lane >> 2);
    int c0 = kc*16 + (lane & 3)*2;
    #define KV(rr, cc) ((rr) < NN ? g_knorm[((size_t)b*NN + (rr))*64 + (cc)] : 0.f)
    float v[8];
    v[0] = KV(row, c0);     v[1] = KV(row, c0+1);
    v[2] = KV(row+8, c0);   v[3] = KV(row+8, c0+1);
    v[4] = KV(row, c0+8);   v[5] = KV(row, c0+9);
    v[6] = KV(row+8, c0+8); v[7] = KV(row+8, c0+9);
    #undef KV
    uint4 o;
    if (sv == 0) {
        o.x = pack_bits(__float2bfloat16(v[0]), __float2bfloat16(v[1]));
        o.y = pack_bits(__float2bfloat16(v[2]), __float2bfloat16(v[3]));
        o.z = pack_bits(__float2bfloat16(v[4]), __float2bfloat16(v[5]));
        o.w = pack_bits(__float2bfloat16(v[6]), __float2bfloat16(v[7]));
    } else {
        o.x = pack_cvt(v[0] - bf_round(v[0]), v[1] - bf_round(v[1]));
        o.y = pack_cvt(v[2] - bf_round(v[2]), v[3] - bf_round(v[3]));
        o.z = pack_cvt(v[4] - bf_round(v[4]), v[5] - bf_round(v[5]));
        o.w = pack_cvt(v[6] - bf_round(v[6]), v[7] - bf_round(v[7]));
    }
    g_kfrag[((b*2 + sv)*4 + kc)*256 + cogrp*32 + lane] = o;
}

// ---------------- Gram: G[b] = MF MF^T (fp32 outer products), msum[b] = col sums ----
// 256 blocks (128/batch x 1024 px), 16x16 thread grid, 4x4 G-tile per thread.
#define G_PX 1024
__global__ __launch_bounds__(256)
void gram_kernel(const float* __restrict__ mf) {
    __shared__ float s[64][68];
    const int b = blockIdx.y;
    const size_t v0 = (size_t)blockIdx.x * G_PX;
    const int tid = threadIdx.x;
    const int ti = tid >> 4, tj = tid & 15;
    const int r0 = ti*4, c0 = tj*4;
    const int mch = tid & 63, mq = tid >> 6;
    float acc[4][4] = {};
    float msacc = 0.f;
    const float* mfb = mf + (size_t)b*64*VV + v0;

    for (int ck = 0; ck < G_PX/64; ck++) {
        __syncthreads();
        #pragma unroll
        for (int it = 0; it < 4; it++) {
            int i = tid + it*256;            // ch = i>>4, p4 = i&15
            int ch = i >> 4, p4 = i & 15;
            float4 v = *(const float4*)(mfb + (size_t)ch*VV + ck*64 + p4*4);
            s[p4*4 + 0][ch] = v.x;
            s[p4*4 + 1][ch] = v.y;
            s[p4*4 + 2][ch] = v.z;
            s[p4*4 + 3][ch] = v.w;
        }
        __syncthreads();
        #pragma unroll 4
        for (int p = 0; p < 64; p++) {
            float4 a = *(const float4*)&s[p][r0];
            float4 c = *(const float4*)&s[p][c0];
            acc[0][0] = fmaf(a.x, c.x, acc[0][0]);
            acc[0][1] = fmaf(a.x, c.y, acc[0][1]);
            acc[0][2] = fmaf(a.x, c.z, acc[0][2]);
            acc[0][3] = fmaf(a.x, c.w, acc[0][3]);
            acc[1][0] = fmaf(a.y, c.x, acc[1][0]);
            acc[1][1] = fmaf(a.y, c.y, acc[1][1]);
            acc[1][2] = fmaf(a.y, c.z, acc[1][2]);
            acc[1][3] = fmaf(a.y, c.w, acc[1][3]);
            acc[2][0] = fmaf(a.z, c.x, acc[2][0]);
            acc[2][1] = fmaf(a.z, c.y, acc[2][1]);
            acc[2][2] = fmaf(a.z, c.z, acc[2][2]);
            acc[2][3] = fmaf(a.z, c.w, acc[2][3]);
            acc[3][0] = fmaf(a.w, c.x, acc[3][0]);
            acc[3][1] = fmaf(a.w, c.y, acc[3][1]);
            acc[3][2] = fmaf(a.w, c.z, acc[3][2]);
            acc[3][3] = fmaf(a.w, c.w, acc[3][3]);
        }
        #pragma unroll
        for (int p = 0; p < 16; p++) msacc += s[mq*16 + p][mch];
    }
    float* Gp = g_gram + b*4096;
    #pragma unroll
    for (int i = 0; i < 4; i++)
        #pragma unroll
        for (int j = 0; j < 4; j++)
            atomicAdd(&Gp[(r0+i)*64 + (c0+j)], acc[i][j]);
    atomicAdd(&g_msum[b*64 + mch], msacc);
}

// ---------------- analytic mask stats -> scale/shift ----------------
__global__ void stats_kernel(const float* __restrict__ gam, const float* __restrict__ bet) {
    __shared__ double sS[256], sQ[256];
    const int tid = threadIdx.x;
    double s = 0.0, q = 0.0;
    if (tid < BB*NN) {
        int b = tid / NN, n = tid % NN;
        const float* K = g_knorm + ((size_t)b*NN + n)*64;
        float kr[64];
        #pragma unroll
        for (int c = 0; c < 64; c++) kr[c] = K[c];
        const float* G = g_gram + b*4096;
        const float* M = g_msum + b*64;
        float qs = 0.f, ss = 0.f;
        #pragma unroll 4
        for (int c = 0; c < 64; c++) {
            float d = 0.f;
            #pragma unroll
            for (int e = 0; e < 64; e++) d = fmaf(G[c*64 + e], kr[e], d);
            qs = fmaf(kr[c], d, qs);
            ss = fmaf(kr[c], M[c], ss);
        }
        s = (double)ss; q = (double)qs;
    }
    sS[tid] = s; sQ[tid] = q;
    __syncthreads();
    for (int st = 128; st > 0; st >>= 1) {
        if (tid < st) { sS[tid] += sS[tid+st]; sQ[tid] += sQ[tid+st]; }
        __syncthreads();
    }
    if (tid == 0) {
        double mean = sS[0] / (double)PM_ELEMS;
        double ex2  = sQ[0] / (double)PM_ELEMS;
        double var  = ex2 - mean*mean;
        float inv = (float)(1.0 / sqrt(var + (double)EPSV));
        float sc = gam[0] * inv;
        g_scaleS = sc;
        g_shiftS = bet[0] - (float)mean * sc;
    }
}

// ---------------- features (ch-major fp32) -> pixel-major bf16 hi/lo ----------------
__global__ __launch_bounds__(256)
void trans_kernel(const float* __restrict__ in, uint16_t* __restrict__ outHi) {
    __shared__ float s[64][129];
    const int blk = blockIdx.x;
    const int sl = blk >> 7;
    const int h  = blk & 127;
    const int b = sl >> 3, d = sl & 7;
    const int tid = threadIdx.x;
    for (int i = tid; i < 8192; i += 256) {
        int c = i >> 7, w = i & 127;
        s[c][w] = in[((size_t)(b*64 + c)*8 + d)*16384 + h*128 + w];
    }
    __syncthreads();
    for (int i = tid; i < 1024; i += 256) {
        int w = i >> 3, ch = i & 7;
        uint32_t hw[4], lw[4];
        #pragma unroll
        for (int j = 0; j < 4; j++) {
            float v0 = s[ch*8 + 2*j][w];
            float v1 = s[ch*8 + 2*j + 1][w];
            __nv_bfloat16 h0 = __float2bfloat16(v0);
            __nv_bfloat16 h1 = __float2bfloat16(v1);
            hw[j] = pack_bits(h0, h1);
            lw[j] = pack_cvt(v0 - __bfloat162float(h0), v1 - __bfloat162float(h1));
        }
        size_t e = (((size_t)sl*128 + h)*128 + w)*64 + ch*8;
        *(uint4*)(outHi + e) = make_uint4(hw[0], hw[1], hw[2], hw[3]);
        *(uint4*)(outHi + HALF_ELEMS + e) = make_uint4(lw[0], lw[1], lw[2], lw[3]);
    }
}

// ================= mma.sync conv: 2 CTAs/SM, A from gmem fragment tables ==========
#define SM_IN    0            // 2 x 50688
#define SM_BIAS  101376
#define CONV_SMEM 101632
#define IN_ROW   8448         // 66 px * 128 B
#define BUF_STRIDE 50688
#define GRIDC 296

__global__ __launch_bounds__(256, 2)
void conv_mma_kernel(const uint16_t* __restrict__ inBuf,
                     void* __restrict__ outP,
                     const uint4* __restrict__ wfragHi,
                     const uint4* __restrict__ wfragLo,
                     const float* __restrict__ bias,
                     int mode)
{
    extern __shared__ char smem[];
    const uint32_t sb = smem_u32(smem);
    float* sBias = (float*)(smem + SM_BIAS);
    const int tid = threadIdx.x;
    const int wid = tid >> 5, lane = tid & 31;

    if (tid < 64) sBias[tid] = bias[tid];
    __syncthreads();

    const int ks      = wid >> 2;
    const int cg2     = (wid >> 1) & 1;
    const int co_base = cg2 * 32;
    const int px_base = (wid & 1) * 32;
    const int bn  = (lane & 7) + (lane >> 4) * 8;
    const int bkh = (lane >> 3) & 1;

    uint32_t meta[13];
    #pragma unroll
    for (int j = 0; j < 13; j++) {
        int i = tid + j*256;
        if (i < 3168) {
            int bsel = (i >= 1584) ? 1 : 0;
            int r = i - bsel*1584;
            int ky = r / 528; int rem = r - ky*528;
            int px = rem >> 3; int ch = rem & 7;
            uint32_t dsto = (uint32_t)(bsel*25344 + ky*IN_ROW + px*128 +
                                       ((ch ^ (px & 7)) << 4));
            meta[j] = dsto | ((uint32_t)ky << 16) | ((uint32_t)px << 18) |
                      ((uint32_t)ch << 25) | ((uint32_t)bsel << 28) | (1u << 31);
        } else meta[j] = 0;
    }

    auto stage_tile = [&](int buf, int t) {
        const int sl = t >> 8;
        const int h  = (t >> 1) & 127;
        const int w0 = (t & 1) << 6;
        const uint32_t dstBase = sb + SM_IN + buf*BUF_STRIDE;
        const uint16_t* base = inBuf + (size_t)sl * 1048576;
        #pragma unroll
        for (int j = 0; j < 13; j++) {
            uint32_t m = meta[j];
            if (m & (1u << 31)) {
                int ky = (m >> 16) & 3;
                int px = (m >> 18) & 127;
                int ch = (m >> 25) & 7;
                int bsel = (m >> 28) & 1;
                int gh = h + ky - 1, gw = w0 + px - 1;
                uint32_t ok = (((unsigned)gh < 128u) & ((unsigned)gw < 128u)) ? 1u : 0u;
                int cgh = ok ? gh : 0, cgw = ok ? gw : 0;
                const uint16_t* src = base + (size_t)bsel*HALF_ELEMS +
                        (((uint32_t)(cgh*128 + cgw)) << 6) + (ch << 3);
                CP_ASYNC16(dstBase + (m & 0xFFFFu), src, ok ? 16u : 0u);
            }
        }
        CP_COMMIT();
    };

    int t = blockIdx.x;
    int curbuf = 0;
    if (t < 4096) stage_tile(0, t);

    for (; t < 4096; t += GRIDC) {
        const int sl = t >> 8;
        const int h  = (t >> 1) & 127;
        const int w0 = (t & 1) << 6;
        const int nt = t + GRIDC;

        if (nt < 4096) { stage_tile(curbuf ^ 1, nt); CP_WAIT1(); }
        else           { CP_WAIT0(); }
        __syncthreads();

        const uint32_t inHi = sb + SM_IN + curbuf*BUF_STRIDE;
        const uint32_t inLo = inHi + 25344;

        float acc[2][4][4] = {};
        #pragma unroll
        for (int ky = 0; ky < 3; ky++) {
            const uint32_t bHrow = inHi + ky*IN_ROW;
            const uint32_t bLrow = inLo + ky*IN_ROW;
            #pragma unroll
            for (int kx = 0; kx < 3; kx++) {
                const int tap = ky*3 + kx;
                const int spx1 = px_base + bn + kx;
                const int spx2 = spx1 + 16;
                const uint32_t bH1 = bHrow + spx1*128;
                const uint32_t bH2 = bHrow + spx2*128;
                const uint32_t bL1 = bLrow + spx1*128;
                const uint32_t bL2 = bLrow + spx2*128;
                const uint32_t bx1 = (uint32_t)((spx1 & 7) << 4);
                const uint32_t bx2 = (uint32_t)((spx2 & 7) << 4);
                const uint4* whp = wfragHi + (tap*4)*128 + lane;
                const uint4* wlp = wfragLo + (tap*4)*128 + lane;
                #pragma unroll
                for (int kc2 = 0; kc2 < 2; kc2++) {
                    const int kc = ks*2 + kc2;
                    const uint32_t kub = (uint32_t)(kc*32 + bkh*16);
                    uint4 ah0 = whp[kc*128 + (2*cg2)*32];
                    uint4 ah1 = whp[kc*128 + (2*cg2 + 1)*32];
                    uint4 al0 = wlp[kc*128 + (2*cg2)*32];
                    uint4 al1 = wlp[kc*128 + (2*cg2 + 1)*32];
                    uint32_t h0,h1,h2,h3, h4,h5,h6,h7;
                    LDSM4(h0,h1,h2,h3, bH1 + (kub ^ bx1));
                    LDSM4(h4,h5,h6,h7, bH2 + (kub ^ bx2));
                    uint32_t l0,l1,l2,l3, l4,l5,l6,l7;
                    LDSM4(l0,l1,l2,l3, bL1 + (kub ^ bx1));
                    LDSM4(l4,l5,l6,l7, bL2 + (kub ^ bx2));
                    MMA16816(acc[0][0], ah0.x,ah0.y,ah0.z,ah0.w, h0,h1);
                    MMA16816(acc[0][1], ah0.x,ah0.y,ah0.z,ah0.w, h2,h3);
                    MMA16816(acc[0][2], ah0.x,ah0.y,ah0.z,ah0.w, h4,h5);
                    MMA16816(acc[0][3], ah0.x,ah0.y,ah0.z,ah0.w, h6,h7);
                    MMA16816(acc[0][0], ah0.x,ah0.y,ah0.z,ah0.w, l0,l1);
                    MMA16816(acc[0][1], ah0.x,ah0.y,ah0.z,ah0.w, l2,l3);
                    MMA16816(acc[0][2], ah0.x,ah0.y,ah0.z,ah0.w, l4,l5);
                    MMA16816(acc[0][3], ah0.x,ah0.y,ah0.z,ah0.w, l6,l7);
                    MMA16816(acc[0][0], al0.x,al0.y,al0.z,al0.w, h0,h1);
                    MMA16816(acc[0][1], al0.x,al0.y,al0.z,al0.w, h2,h3);
                    MMA16816(acc[0][2], al0.x,al0.y,al0.z,al0.w, h4,h5);
                    MMA16816(acc[0][3], al0.x,al0.y,al0.z,al0.w, h6,h7);
                    MMA16816(acc[1][0], ah1.x,ah1.y,ah1.z,ah1.w, h0,h1);
                    MMA16816(acc[1][1], ah1.x,ah1.y,ah1.z,ah1.w, h2,h3);
                    MMA16816(acc[1][2], ah1.x,ah1.y,ah1.z,ah1.w, h4,h5);
                    MMA16816(acc[1][3], ah1.x,ah1.y,ah1.z,ah1.w, h6,h7);
                    MMA16816(acc[1][0], ah1.x,ah1.y,ah1.z,ah1.w, l0,l1);
                    MMA16816(acc[1][1], ah1.x,ah1.y,ah1.z,ah1.w, l2,l3);
                    MMA16816(acc[1][2], ah1.x,ah1.y,ah1.z,ah1.w, l4,l5);
                    MMA16816(acc[1][3], ah1.x,ah1.y,ah1.z,ah1.w, l6,l7);
                    MMA16816(acc[1][0], al1.x,al1.y,al1.z,al1.w, h0,h1);
                    MMA16816(acc[1][1], al1.x,al1.y,al1.z,al1.w, h2,h3);
                    MMA16816(acc[1][2], al1.x,al1.y,al1.z,al1.w, h4,h5);
                    MMA16816(acc[1][3], al1.x,al1.y,al1.z,al1.w, h6,h7);
                }
            }
        }
        __syncthreads();

        float* Sbase = (float*)(smem + SM_IN + curbuf*BUF_STRIDE);
        float* Sw = Sbase + ks*4160;
        #pragma unroll
        for (int mt = 0; mt < 2; mt++) {
            #pragma unroll
            for (int j = 0; j < 4; j++) {
                int pc = px_base + 8*j + 2*(lane & 3);
                int mr = co_base + mt*16 + (lane >> 2);
                Sw[pc*65 + mr]           = acc[mt][j][0];
                Sw[(pc+1)*65 + mr]       = acc[mt][j][1];
                Sw[pc*65 + mr + 8]       = acc[mt][j][2];
                Sw[(pc+1)*65 + mr + 8]   = acc[mt][j][3];
            }
        }
        __syncthreads();

        const float* S0 = Sbase;
        const float* S1 = Sbase + 4160;
        if (mode == 0) {
            const int px = tid >> 2, cb = (tid & 3) * 16;
            uint32_t hw[8], lw[8];
            #pragma unroll
            for (int j = 0; j < 8; j++) {
                int i0 = px*65 + cb + 2*j;
                float v0 = fmaxf(S0[i0]     + S1[i0]     + sBias[cb + 2*j],     0.f);
                float v1 = fmaxf(S0[i0 + 1] + S1[i0 + 1] + sBias[cb + 2*j + 1], 0.f);
                __nv_bfloat16 h0 = __float2bfloat16(v0);
                __nv_bfloat16 h1 = __float2bfloat16(v1);
                hw[j] = pack_bits(h0, h1);
                lw[j] = pack_cvt(v0 - __bfloat162float(h0), v1 - __bfloat162float(h1));
            }
            uint16_t* ob = (uint16_t*)outP;
            size_t e = (((size_t)sl*128 + h)*128 + (w0 + px))*64 + cb;
            *(uint4*)(ob + e)     = make_uint4(hw[0], hw[1], hw[2], hw[3]);
            *(uint4*)(ob + e + 8) = make_uint4(hw[4], hw[5], hw[6], hw[7]);
            *(uint4*)(ob + HALF_ELEMS + e)     = make_uint4(lw[0], lw[1], lw[2], lw[3]);
            *(uint4*)(ob + HALF_ELEMS + e + 8) = make_uint4(lw[4], lw[5], lw[6], lw[7]);
        } else {
            const int co = tid >> 2, pb = (tid & 3) * 16;
            const int b_ = sl >> 3, d_ = sl & 7;
            const float bv = sBias[co];
            float* ob = (float*)outP +
                ((size_t)(b_*64 + co)*8 + d_)*16384 + h*128 + w0 + pb;
            #pragma unroll
            for (int q = 0; q < 4; q++) {
                float4 o;
                int i0 = (pb + 4*q)*65 + co;
                o.x = fmaxf(S0[i0]        + S1[i0]        + bv, 0.f);
                o.y = fmaxf(S0[i0 + 65]   + S1[i0 + 65]   + bv, 0.f);
                o.z = fmaxf(S0[i0 + 130]  + S1[i0 + 130]  + bv, 0.f);
                o.w = fmaxf(S0[i0 + 195]  + S1[i0 + 195]  + bv, 0.f);
                *(float4*)(ob + 4*q) = o;
            }
        }
        __syncthreads();
        curbuf ^= 1;
    }
}

// ---------------- segment sums ----------------
#define VCH 2048
__global__ __launch_bounds__(256)
void segsum_kernel(const float* __restrict__ x, const int* __restrict__ labels)
{
    __shared__ float sAcc[LL*CC];
    __shared__ float sCnt[LL];
    __shared__ int sLab[VCH];
    const int b = blockIdx.y;
    const int v0 = blockIdx.x * VCH;
    const int tid = threadIdx.x;

    for (int i = tid; i < LL*CC; i += 256) sAcc[i] = 0.f;
    for (int i = tid; i < LL; i += 256) sCnt[i] = 0.f;
    for (int i = tid; i < VCH; i += 256) sLab[i] = labels[(size_t)b*VV + v0 + i];
    __syncthreads();

    for (int i = tid; i < VCH; i += 256) atomicAdd(&sCnt[sLab[i]], 1.f);
    const float* xb = x + (size_t)b*64*VV + v0;
    for (int c = 0; c < 64; c++) {
        const float* xc = xb + (size_t)c*VV;
        for (int i = tid; i < VCH; i += 256)
            atomicAdd(&sAcc[sLab[i]*64 + c], xc[i]);
    }
    __syncthreads();
    for (int i = tid; i < LL*CC; i += 256) atomicAdd(&g_sums[b*LL*CC + i], sAcc[i]);
    for (int i = tid; i < LL; i += 256) atomicAdd(&g_counts[b*LL + i], sCnt[i]);
}

// ---------------- inst features + mask_kernel linear ----------------
__global__ __launch_bounds__(256)
void instfeat_kernel(const float* __restrict__ embed, const float* __restrict__ mk_w,
                     const float* __restrict__ mk_b, float* __restrict__ if_out,
                     int write_if)
{
    __shared__ float sInst[NN*CC];
    __shared__ float sWT[CC*KD];
    const int b = blockIdx.x;
    const int tid = threadIdx.x;

    for (int idx = tid; idx < CC*KD; idx += 256) {
        int kd = idx & 63, c = idx >> 6;
        sWT[c*64 + kd] = mk_w[kd*64 + c];
    }
    for (int idx = tid; idx < 100*CC; idx += 256) {
        int n = idx >> 6, c = idx & 63;
        int l = n + 1;
        float cnt = fmaxf(g_counts[b*LL + l], 1.f);
        sInst[idx] = g_sums[(b*LL + l)*64 + c] / cnt;
    }
    for (int idx = tid; idx < NLM*CC; idx += 256)
        sInst[100*CC + idx] = embed[idx];
    __syncthreads();

    if (write_if)
        for (int idx = tid; idx < NN*CC; idx += 256)
            if_out[(size_t)b*NN*CC + idx] = sInst[idx];

    for (int idx = tid; idx < NN*KD; idx += 256) {
        int n = idx >> 6, kd = idx & 63;
        const float* ip = sInst + n*64;
        float a = mk_b[kd];
        #pragma unroll
        for (int c = 0; c < 64; c++)
            a = fmaf(ip[c], sWT[c*64 + kd], a);
        g_kraw[(size_t)b*NN*KD + idx] = a;
    }
}

// ---------------- BatchNorm1d over (B,N) per KD channel (parallel) ----------------
__global__ __launch_bounds__(256)
void bnk_kernel(const float* __restrict__ gamma, const float* __restrict__ beta,
                float* __restrict__ pk_out, int write_pk)
{
    __shared__ float ssum[256], ssq[256];
    __shared__ float sm[64], si[64], sg[64], sbt[64];
    const int tid = threadIdx.x;
    const int kd = tid & 63, q = tid >> 6;
    float s = 0.f, sq = 0.f;
    for (int i = q; i < BB*NN; i += 4) {
        float v = g_kraw[i*64 + kd];
        s += v; sq += v*v;
    }
    ssum[tid] = s; ssq[tid] = sq;
    __syncthreads();
    if (tid < 64) {
        float S = ssum[tid] + ssum[tid+64] + ssum[tid+128] + ssum[tid+192];
        float Q = ssq[tid] + ssq[tid+64] + ssq[tid+128] + ssq[tid+192];
        float mean = S / (float)(BB*NN);
        float var = Q / (float)(BB*NN) - mean*mean;
        sm[tid] = mean;
        si[tid] = rsqrtf(var + EPSV);
        sg[tid] = gamma[tid];
        sbt[tid] = beta[tid];
    }
    __syncthreads();
    for (int e = tid; e < BB*NN*KD; e += 256) {
        int k2 = e & 63;
        float v = (g_kraw[e] - sm[k2]) * si[k2] * sg[k2] + sbt[k2];
        g_knorm[e] = v;
        if (write_pk) pk_out[e] = v;
    }
}

// ---------------- bmm via mma.sync with fused normalization ----------------
#define BM_BH 0
#define BM_BL 8192
#define BM_S  16384
#define BMM_SMEM (16384 + 33280)      // 49664

__global__ __launch_bounds__(256)
void bmm_mma_kernel(const float* __restrict__ mf, float* __restrict__ pm)
{
    extern __shared__ char bsm[];
    const uint32_t sb = smem_u32(bsm);
    float* S = (float*)(bsm + BM_S);
    const int b = blockIdx.y;
    const int v0 = blockIdx.x * 64;
    const int tid = threadIdx.x;
    const int wid = tid >> 5, lane = tid & 31;

    {
        const float* mb = mf + ((size_t)(b*64 + 8*wid))*VV + v0;
        #pragma unroll
        for (int it = 0; it < 2; it++) {
            const int px = lane + it*32;
            float x[8];
            #pragma unroll
            for (int kk = 0; kk < 8; kk++)
                x[kk] = mb[(size_t)kk*VV + px];
            uint32_t hw[4], lw[4];
            #pragma unroll
            for (int j = 0; j < 4; j++) {
                float a = x[2*j], c = x[2*j + 1];
                __nv_bfloat16 ha = __float2bfloat16(a);
                __nv_bfloat16 hc = __float2bfloat16(c);
                hw[j] = pack_bits(ha, hc);
                lw[j] = pack_cvt(a - __bfloat162float(ha), c - __bfloat162float(hc));
            }
            uint32_t addr = (uint32_t)(px*128 + ((wid ^ (px & 7)) << 4));
            asm volatile("st.shared.v4.b32 [%0], {%1,%2,%3,%4};"
                :: "r"(sb + BM_BH + addr), "r"(hw[0]), "r"(hw[1]), "r"(hw[2]), "r"(hw[3]) : "memory");
            asm volatile("st.shared.v4.b32 [%0], {%1,%2,%3,%4};"
                :: "r"(sb + BM_BL + addr), "r"(lw[0]), "r"(lw[1]), "r"(lw[2]), "r"(lw[3]) : "memory");
        }
    }
    __syncthreads();

    const int mgrp = wid >> 1;
    const int pxg  = wid & 1;
    const int bn  = (lane & 7) + (lane >> 4) * 8;
    const int bkh = (lane >> 3) & 1;
    const int spx1 = pxg*32 + bn;
    const int spx2 = spx1 + 16;
    const uint32_t bH1 = sb + BM_BH + spx1*128;
    const uint32_t bH2 = sb + BM_BH + spx2*128;
    const uint32_t bL1 = sb + BM_BL + spx1*128;
    const uint32_t bL2 = sb + BM_BL + spx2*128;
    const uint32_t bx1 = (uint32_t)((spx1 & 7) << 4);
    const uint32_t bx2 = (uint32_t)((spx2 & 7) << 4);
    const uint4* khp = g_kfrag + (b*2 + 0)*1024;
    const uint4* klp = g_kfrag + (b*2 + 1)*1024;

    float acc[2][4][4] = {};
    #pragma unroll
    for (int kc = 0; kc < 4; kc++) {
        const uint32_t kub = (uint32_t)(kc*32 + bkh*16);
        uint4 ah0 = khp[kc*256 + (mgrp*2)*32 + lane];
        uint4 ah1 = khp[kc*256 + (mgrp*2 + 1)*32 + lane];
        uint4 al0 = klp[kc*256 + (mgrp*2)*32 + lane];
        uint4 al1 = klp[kc*256 + (mgrp*2 + 1)*32 + lane];
        uint32_t h0,h1,h2,h3, h4,h5,h6,h7;
        LDSM4(h0,h1,h2,h3, bH1 + (kub ^ bx1));
        LDSM4(h4,h5,h6,h7, bH2 + (kub ^ bx2));
        uint32_t l0,l1,l2,l3, l4,l5,l6,l7;
        LDSM4(l0,l1,l2,l3, bL1 + (kub ^ bx1));
        LDSM4(l4,l5,l6,l7, bL2 + (kub ^ bx2));
        MMA16816(acc[0][0], ah0.x,ah0.y,ah0.z,ah0.w, h0,h1);
        MMA16816(acc[0][1], ah0.x,ah0.y,ah0.z,ah0.w, h2,h3);
        MMA16816(acc[0][2], ah0.x,ah0.y,ah0.z,ah0.w, h4,h5);
        MMA16816(acc[0][3], ah0.x,ah0.y,ah0.z,ah0.w, h6,h7);
        MMA16816(acc[0][0], ah0.x,ah0.y,ah0.z,ah0.w, l0,l1);
        MMA16816(acc[0][1], ah0.x,ah0.y,ah0.z,ah0.w, l2,l3);
        MMA16816(acc[0][2], ah0.x,ah0.y,ah0.z,ah0.w, l4,l5);
        MMA16816(acc[0][3], ah0.x,ah0.y,ah0.z,ah0.w, l6,l7);
        MMA16816(acc[0][0], al0.x,al0.y,al0.z,al0.w, h0,h1);
        MMA16816(acc[0][1], al0.x,al0.y,al0.z,al0.w, h2,h3);
        MMA16816(acc[0][2], al0.x,al0.y,al0.z,al0.w, h4,h5);
        MMA16816(acc[0][3], al0.x,al0.y,al0.z,al0.w, h6,h7);
        MMA16816(acc[1][0], ah1.x,ah1.y,ah1.z,ah1.w, h0,h1);
        MMA16816(acc[1][1], ah1.x,ah1.y,ah1.z,ah1.w, h2,h3);
        MMA16816(acc[1][2], ah1.x,ah1.y,ah1.z,ah1.w, h4,h5);
        MMA16816(acc[1][3], ah1.x,ah1.y,ah1.z,ah1.w, h6,h7);
        MMA16816(acc[1][0], ah1.x,ah1.y,ah1.z,ah1.w, l0,l1);
        MMA16816(acc[1][1], ah1.x,ah1.y,ah1.z,ah1.w, l2,l3);
        MMA16816(acc[1][2], ah1.x,ah1.y,ah1.z,ah1.w, l4,l5);
        MMA16816(acc[1][3], ah1.x,ah1.y,ah1.z,ah1.w, l6,l7);
        MMA16816(acc[1][0], al1.x,al1.y,al1.z,al1.w, h0,h1);
        MMA16816(acc[1][1], al1.x,al1.y,al1.z,al1.w, h2,h3);
        MMA16816(acc[1][2], al1.x,al1.y,al1.z,al1.w, h4,h5);
        MMA16816(acc[1][3], al1.x,al1.y,al1.z,al1.w, h6,h7);
    }

    #pragma unroll
    for (int mt = 0; mt < 2; mt++) {
        #pragma unroll
        for (int j = 0; j < 4; j++) {
            int pc = pxg*32 + 8*j + 2*(lane & 3);
            int mr = mgrp*32 + mt*16 + (lane >> 2);
            S[mr*65 + pc]           = acc[mt][j][0];
            S[mr*65 + pc + 1]       = acc[mt][j][1];
            S[(mr+8)*65 + pc]       = acc[mt][j][2];
            S[(mr+8)*65 + pc + 1]   = acc[mt][j][3];
        }
    }
    __syncthreads();

    // write normalized masks
    const float sc = g_scaleS, sh = g_shiftS;
    float* po = pm + (size_t)b*NN*VV + v0;
    for (int idx = tid; idx < NN*64; idx += 256) {
        int n = idx >> 6, px = idx & 63;
        po[(size_t)n*VV + px] = S[n*65 + px] * sc + sh;
    }
}

// ---------------- launch ----------------
extern "C" void kernel_launch(void* const* d_in, const int* in_sizes, int n_in,
                              void* d_out, int out_size)
{
    const float* features      = (const float*)d_in[0];
    const float* mask_features = (const float*)d_in[1];
    const float* conv_w        = (const float*)d_in[2];
    const float* conv_b        = (const float*)d_in[3];
    const float* embed         = (const float*)d_in[4];
    const float* mk_w          = (const float*)d_in[5];
    const float* mk_b          = (const float*)d_in[6];
    const float* nk_gamma      = (const float*)d_in[7];
    const float* nk_beta       = (const float*)d_in[8];
    const float* nl_gamma      = (const float*)d_in[9];
    const float* nl_beta       = (const float*)d_in[10];
    const int*   init_masks    = (const int*)d_in[11];
    float* out = (float*)d_out;

    float *bufA = nullptr, *bufB = nullptr;
    uint4 *wfragHi = nullptr, *wfragLo = nullptr;
    cudaGetSymbolAddress((void**)&bufA, g_bufA);
    cudaGetSymbolAddress((void**)&bufB, g_bufB);
    cudaGetSymbolAddress((void**)&wfragHi, g_wfragHi);
    cudaGetSymbolAddress((void**)&wfragLo, g_wfragLo);
    uint16_t* hA = (uint16_t*)bufA;
    uint16_t* hB = (uint16_t*)bufB;

    int full = (out_size >= OUT_FULL) ? 1 : 0;
    int masks_only = (!full && out_size >= PM_ELEMS) ? 1 : 0;

    float* xout  = full ? out : bufB;
    float* ifout = full ? (out + X_ELEMS) : out;
    float* pmout = full ? (out + X_ELEMS + IF_ELEMS) : (masks_only ? out : bufB);
    float* pkout = full ? (out + X_ELEMS + IF_ELEMS + PM_ELEMS) : out;

    static int attr_done = 0;
    if (!attr_done) {
        cudaFuncSetAttribute(conv_mma_kernel,
                             cudaFuncAttributeMaxDynamicSharedMemorySize, CONV_SMEM);
        cudaFuncSetAttribute(bmm_mma_kernel,
                             cudaFuncAttributeMaxDynamicSharedMemorySize, BMM_SMEM);
        attr_done = 1;
    }

    init_zero_kernel<<<1, 256>>>();
    wfrag_kernel<<<72, 256>>>(conv_w);
    trans_kernel<<<2048, 256>>>(features, hB);

    conv_mma_kernel<<<GRIDC, 256, CONV_SMEM>>>(hB, hA,   wfragHi + 0*4608, wfragLo + 0*4608, conv_b + 0,   0);
    conv_mma_kernel<<<GRIDC, 256, CONV_SMEM>>>(hA, hB,   wfragHi + 1*4608, wfragLo + 1*4608, conv_b + 64,  0);
    conv_mma_kernel<<<GRIDC, 256, CONV_SMEM>>>(hB, hA,   wfragHi + 2*4608, wfragLo + 2*4608, conv_b + 128, 0);
    conv_mma_kernel<<<GRIDC, 256, CONV_SMEM>>>(hA, xout, wfragHi + 3*4608, wfragLo + 3*4608, conv_b + 192, 1);

    segsum_kernel<<<dim3(VV/VCH, BB), 256>>>(xout, init_masks);
    instfeat_kernel<<<BB, 256>>>(embed, mk_w, mk_b, ifout, full);
    bnk_kernel<<<1, 256>>>(nk_gamma, nk_beta, pkout, full);

    if (full || masks_only) {
        gram_kernel<<<dim3(VV/G_PX, BB), 256>>>(mask_features);
        kfrag_kernel<<<16, 256>>>();
        stats_kernel<<<1, 256>>>(nl_gamma, nl_beta);
        bmm_mma_kernel<<<dim3(VV/64, BB), 256, BMM_SMEM>>>(mask_features, pmout);
    }
}

// round 15
// speedup vs baseline: 1.2475x; 1.1364x over previous
#include <cuda_runtime.h>
#include <cuda_bf16.h>
#include <math.h>
#include <stdint.h>

// Problem constants
#define BB 2
#define CC 64
#define DD 8
#define HH 128
#define WW 128
#define VV (DD*HH*WW)          // 131072
#define LL 101
#define KD 64
#define NLM 20
#define NN (100 + NLM)         // 120
#define EPSV 1e-3f

#define X_ELEMS   (BB*CC*VV)          // 16777216
#define IF_ELEMS  (BB*NN*CC)
#define PM_ELEMS  (BB*NN*VV)
#define PK_ELEMS  (BB*NN*KD)
#define OUT_FULL  (X_ELEMS + IF_ELEMS + PM_ELEMS + PK_ELEMS)

#define HALF_ELEMS 16777216           // bf16 elems per (hi|lo) half of a scratch buffer

// ---------------- device scratch ----------------
__device__ float g_bufA[X_ELEMS];     // Hi bf16 [0..16M) + Lo bf16 [16M..32M)
__device__ float g_bufB[X_ELEMS];
__device__ uint4 g_wfragHi[4*9*4*4*32];   // Whi in mma-A fragment order
__device__ uint4 g_wfragLo[4*9*4*4*32];   // Wlo in mma-A fragment order
__device__ uint4 g_kfrag[4096];           // knorm frags: [b][sv][kc][cogrp][lane]
__device__ float g_sums[BB*LL*CC];
__device__ float g_counts[BB*LL];
__device__ float g_kraw[BB*NN*KD];
__device__ float g_knorm[BB*NN*KD];
__device__ double g_psum;
__device__ double g_psumsq;

// ================= helpers =================
typedef unsigned long long u64t;
__device__ __forceinline__ uint32_t smem_u32(const void* p) {
    uint32_t a;
    asm("{ .reg .u64 t; cvta.to.shared.u64 t, %1; cvt.u32.u64 %0, t; }"
        : "=r"(a) : "l"(p));
    return a;
}
__device__ __forceinline__ uint32_t pack_bits(__nv_bfloat16 lo, __nv_bfloat16 hi) {
    return (uint32_t)__bfloat16_as_ushort(lo) | ((uint32_t)__bfloat16_as_ushort(hi) << 16);
}
__device__ __forceinline__ uint32_t pack_cvt(float lo, float hi) {
    uint32_t r;
    asm("cvt.rn.bf16x2.f32 %0, %1, %2;" : "=r"(r) : "f"(hi), "f"(lo));
    return r;
}
__device__ __forceinline__ float bf_round(float x) {
    return __bfloat162float(__float2bfloat16(x));
}

#define LDSM4(r0,r1,r2,r3, addr) \
    asm volatile("ldmatrix.sync.aligned.m8n8.x4.shared.b16 {%0,%1,%2,%3}, [%4];" \
        : "=r"(r0),"=r"(r1),"=r"(r2),"=r"(r3) : "r"(addr))

#define MMA16816(d, a0,a1,a2,a3, b0,b1) \
    asm volatile("mma.sync.aligned.m16n8k16.row.col.f32.bf16.bf16.f32 " \
        "{%0,%1,%2,%3}, {%4,%5,%6,%7}, {%8,%9}, {%0,%1,%2,%3};" \
        : "+f"((d)[0]), "+f"((d)[1]), "+f"((d)[2]), "+f"((d)[3]) \
        : "r"(a0),"r"(a1),"r"(a2),"r"(a3), "r"(b0),"r"(b1))

#define CP_ASYNC16(dst, src, n) \
    asm volatile("cp.async.cg.shared.global [%0], [%1], 16, %2;" \
        :: "r"(dst), "l"(src), "r"(n) : "memory")
#define CP_COMMIT() asm volatile("cp.async.commit_group;" ::: "memory")
#define CP_WAIT0()  asm volatile("cp.async.wait_group 0;" ::: "memory")
#define CP_WAIT1()  asm volatile("cp.async.wait_group 1;" ::: "memory")

// ---------------- init ----------------
__global__ void init_zero_kernel() {
    int tid = threadIdx.x;
    if (tid == 0) { g_psum = 0.0; g_psumsq = 0.0; }
    for (int i = tid; i < BB*LL*CC; i += 256) g_sums[i] = 0.f;
    for (int i = tid; i < BB*LL; i += 256) g_counts[i] = 0.f;
}

// ---------------- W -> mma A-fragment order, hi+lo tables (all 4 layers) ----------------
__global__ void wfrag_kernel(const float* __restrict__ w) {
    int idx = blockIdx.x * 256 + threadIdx.x;
    if (idx >= 18432) return;
    int lane = idx & 31;
    int r = idx >> 5;
    int cogrp = r & 3; r >>= 2;
    int kc = r & 3; r >>= 2;
    int tap = r % 9; int l = r / 9;
    int row = cogrp*16 + (lane >> 2);
    int c0 = kc*16 + (lane & 3)*2;
    float v[8];
    v[0] = w[((size_t)(l*64 + row)*64     + c0)*9 + tap];
    v[1] = w[((size_t)(l*64 + row)*64     + c0 + 1)*9 + tap];
    v[2] = w[((size_t)(l*64 + row + 8)*64 + c0)*9 + tap];
    v[3] = w[((size_t)(l*64 + row + 8)*64 + c0 + 1)*9 + tap];
    v[4] = w[((size_t)(l*64 + row)*64     + c0 + 8)*9 + tap];
    v[5] = w[((size_t)(l*64 + row)*64     + c0 + 9)*9 + tap];
    v[6] = w[((size_t)(l*64 + row + 8)*64 + c0 + 8)*9 + tap];
    v[7] = w[((size_t)(l*64 + row + 8)*64 + c0 + 9)*9 + tap];
    uint4 hi, lo;
    hi.x = pack_bits(__float2bfloat16(v[0]), __float2bfloat16(v[1]));
    hi.y = pack_bits(__float2bfloat16(v[2]), __float2bfloat16(v[3]));
    hi.z = pack_bits(__float2bfloat16(v[4]), __float2bfloat16(v[5]));
    hi.w = pack_bits(__float2bfloat16(v[6]), __float2bfloat16(v[7]));
    lo.x = pack_cvt(v[0] - bf_round(v[0]), v[1] - bf_round(v[1]));
    lo.y = pack_cvt(v[2] - bf_round(v[2]), v[3] - bf_round(v[3]));
    lo.z = pack_cvt(v[4] - bf_round(v[4]), v[5] - bf_round(v[5]));
    lo.w = pack_cvt(v[6] - bf_round(v[6]), v[7] - bf_round(v[7]));
    int off = ((l*9 + tap)*4 + kc)*128 + cogrp*32 + lane;
    g_wfragHi[off] = hi;
    g_wfragLo[off] = lo;
}

// ---------------- knorm -> mma A-fragment order, hi+lo (both batches) ----------------
// g_kfrag[((b*2 + sv)*4 + kc)*256 + cogrp*32 + lane], M=128 (rows >=120 zero)
__global__ void kfrag_kernel() {
    int idx = blockIdx.x * 256 + threadIdx.x;
    if (idx >= 4096) return;
    int lane = idx & 31;
    int r = idx >> 5;
    int cogrp = r & 7; r >>= 3;
    int kc = r & 3; r >>= 2;
    int sv = r & 1; int b = r >> 1;
    int row = cogrp*16 + (lane >> 2);
    int c0 = kc*16 + (lane & 3)*2;
    #define KV(rr, cc) ((rr) < NN ? g_knorm[((size_t)b*NN + (rr))*64 + (cc)] : 0.f)
    float v[8];
    v[0] = KV(row, c0);     v[1] = KV(row, c0+1);
    v[2] = KV(row+8, c0);   v[3] = KV(row+8, c0+1);
    v[4] = KV(row, c0+8);   v[5] = KV(row, c0+9);
    v[6] = KV(row+8, c0+8); v[7] = KV(row+8, c0+9);
    #undef KV
    uint4 o;
    if (sv == 0) {
        o.x = pack_bits(__float2bfloat16(v[0]), __float2bfloat16(v[1]));
        o.y = pack_bits(__float2bfloat16(v[2]), __float2bfloat16(v[3]));
        o.z = pack_bits(__float2bfloat16(v[4]), __float2bfloat16(v[5]));
        o.w = pack_bits(__float2bfloat16(v[6]), __float2bfloat16(v[7]));
    } else {
        o.x = pack_cvt(v[0] - bf_round(v[0]), v[1] - bf_round(v[1]));
        o.y = pack_cvt(v[2] - bf_round(v[2]), v[3] - bf_round(v[3]));
        o.z = pack_cvt(v[4] - bf_round(v[4]), v[5] - bf_round(v[5]));
        o.w = pack_cvt(v[6] - bf_round(v[6]), v[7] - bf_round(v[7]));
    }
    g_kfrag[((b*2 + sv)*4 + kc)*256 + cogrp*32 + lane] = o;
}

// ---------------- features (ch-major fp32) -> pixel-major bf16 hi/lo ----------------
__global__ __launch_bounds__(256)
void trans_kernel(const float* __restrict__ in, uint16_t* __restrict__ outHi) {
    __shared__ float s[64][129];
    const int blk = blockIdx.x;
    const int sl = blk >> 7;
    const int h  = blk & 127;
    const int b = sl >> 3, d = sl & 7;
    const int tid = threadIdx.x;
    for (int i = tid; i < 8192; i += 256) {
        int c = i >> 7, w = i & 127;
        s[c][w] = in[((size_t)(b*64 + c)*8 + d)*16384 + h*128 + w];
    }
    __syncthreads();
    for (int i = tid; i < 1024; i += 256) {
        int w = i >> 3, ch = i & 7;
        uint32_t hw[4], lw[4];
        #pragma unroll
        for (int j = 0; j < 4; j++) {
            float v0 = s[ch*8 + 2*j][w];
            float v1 = s[ch*8 + 2*j + 1][w];
            __nv_bfloat16 h0 = __float2bfloat16(v0);
            __nv_bfloat16 h1 = __float2bfloat16(v1);
            hw[j] = pack_bits(h0, h1);
            lw[j] = pack_cvt(v0 - __bfloat162float(h0), v1 - __bfloat162float(h1));
        }
        size_t e = (((size_t)sl*128 + h)*128 + w)*64 + ch*8;
        *(uint4*)(outHi + e) = make_uint4(hw[0], hw[1], hw[2], hw[3]);
        *(uint4*)(outHi + HALF_ELEMS + e) = make_uint4(lw[0], lw[1], lw[2], lw[3]);
    }
}

// ================= mma.sync conv: 2 CTAs/SM, A from gmem fragment tables ==========
// M32xN32 warp tile, K-split 2; S staged into the just-consumed IN buffer.
// Odd CTAs pre-stage their first tile once (idempotent) to desync the two
// co-resident CTAs' phase timing so MMA phases cover epilogue phases.
#define SM_IN    0            // 2 x 50688
#define SM_BIAS  101376
#define CONV_SMEM 101632
#define IN_ROW   8448         // 66 px * 128 B
#define BUF_STRIDE 50688
#define GRIDC 296

__global__ __launch_bounds__(256, 2)
void conv_mma_kernel(const uint16_t* __restrict__ inBuf,   // Hi, Lo at +HALF_ELEMS
                     void* __restrict__ outP,
                     const uint4* __restrict__ wfragHi,
                     const uint4* __restrict__ wfragLo,
                     const float* __restrict__ bias,
                     int mode)
{
    extern __shared__ char smem[];
    const uint32_t sb = smem_u32(smem);
    float* sBias = (float*)(smem + SM_BIAS);
    const int tid = threadIdx.x;
    const int wid = tid >> 5, lane = tid & 31;

    if (tid < 64) sBias[tid] = bias[tid];
    __syncthreads();

    const int ks      = wid >> 2;
    const int cg2     = (wid >> 1) & 1;
    const int co_base = cg2 * 32;
    const int px_base = (wid & 1) * 32;
    const int bn  = (lane & 7) + (lane >> 4) * 8;
    const int bkh = (lane >> 3) & 1;

    uint32_t meta[13];
    #pragma unroll
    for (int j = 0; j < 13; j++) {
        int i = tid + j*256;
        if (i < 3168) {
            int bsel = (i >= 1584) ? 1 : 0;
            int r = i - bsel*1584;
            int ky = r / 528; int rem = r - ky*528;
            int px = rem >> 3; int ch = rem & 7;
            uint32_t dsto = (uint32_t)(bsel*25344 + ky*IN_ROW + px*128 +
                                       ((ch ^ (px & 7)) << 4));
            meta[j] = dsto | ((uint32_t)ky << 16) | ((uint32_t)px << 18) |
                      ((uint32_t)ch << 25) | ((uint32_t)bsel << 28) | (1u << 31);
        } else meta[j] = 0;
    }

    auto stage_tile = [&](int buf, int t) {
        const int sl = t >> 8;
        const int h  = (t >> 1) & 127;
        const int w0 = (t & 1) << 6;
        const uint32_t dstBase = sb + SM_IN + buf*BUF_STRIDE;
        const uint16_t* base = inBuf + (size_t)sl * 1048576;
        #pragma unroll
        for (int j = 0; j < 13; j++) {
            uint32_t m = meta[j];
            if (m & (1u << 31)) {
                int ky = (m >> 16) & 3;
                int px = (m >> 18) & 127;
                int ch = (m >> 25) & 7;
                int bsel = (m >> 28) & 1;
                int gh = h + ky - 1, gw = w0 + px - 1;
                uint32_t ok = (((unsigned)gh < 128u) & ((unsigned)gw < 128u)) ? 1u : 0u;
                int cgh = ok ? gh : 0, cgw = ok ? gw : 0;
                const uint16_t* src = base + (size_t)bsel*HALF_ELEMS +
                        (((uint32_t)(cgh*128 + cgw)) << 6) + (ch << 3);
                CP_ASYNC16(dstBase + (m & 0xFFFFu), src, ok ? 16u : 0u);
            }
        }
        CP_COMMIT();
    };

    int t = blockIdx.x;
    int curbuf = 0;

    // desync: odd CTAs burn one staging latency up-front (idempotent writes)
    if ((blockIdx.x & 1) && t < 4096) {
        stage_tile(0, t);
        CP_WAIT0();
    }

    if (t < 4096) stage_tile(0, t);

    for (; t < 4096; t += GRIDC) {
        const int sl = t >> 8;
        const int h  = (t >> 1) & 127;
        const int w0 = (t & 1) << 6;
        const int nt = t + GRIDC;

        if (nt < 4096) { stage_tile(curbuf ^ 1, nt); CP_WAIT1(); }
        else           { CP_WAIT0(); }
        __syncthreads();

        const uint32_t inHi = sb + SM_IN + curbuf*BUF_STRIDE;
        const uint32_t inLo = inHi + 25344;

        float acc[2][4][4] = {};
        #pragma unroll
        for (int ky = 0; ky < 3; ky++) {
            const uint32_t bHrow = inHi + ky*IN_ROW;
            const uint32_t bLrow = inLo + ky*IN_ROW;
            #pragma unroll
            for (int kx = 0; kx < 3; kx++) {
                const int tap = ky*3 + kx;
                const int spx1 = px_base + bn + kx;
                const int spx2 = spx1 + 16;
                const uint32_t bH1 = bHrow + spx1*128;
                const uint32_t bH2 = bHrow + spx2*128;
                const uint32_t bL1 = bLrow + spx1*128;
                const uint32_t bL2 = bLrow + spx2*128;
                const uint32_t bx1 = (uint32_t)((spx1 & 7) << 4);
                const uint32_t bx2 = (uint32_t)((spx2 & 7) << 4);
                const uint4* whp = wfragHi + (tap*4)*128 + lane;
                const uint4* wlp = wfragLo + (tap*4)*128 + lane;
                #pragma unroll
                for (int kc2 = 0; kc2 < 2; kc2++) {
                    const int kc = ks*2 + kc2;
                    const uint32_t kub = (uint32_t)(kc*32 + bkh*16);
                    uint4 ah0 = whp[kc*128 + (2*cg2)*32];
                    uint4 ah1 = whp[kc*128 + (2*cg2 + 1)*32];
                    uint4 al0 = wlp[kc*128 + (2*cg2)*32];
                    uint4 al1 = wlp[kc*128 + (2*cg2 + 1)*32];
                    uint32_t h0,h1,h2,h3, h4,h5,h6,h7;
                    LDSM4(h0,h1,h2,h3, bH1 + (kub ^ bx1));
                    LDSM4(h4,h5,h6,h7, bH2 + (kub ^ bx2));
                    uint32_t l0,l1,l2,l3, l4,l5,l6,l7;
                    LDSM4(l0,l1,l2,l3, bL1 + (kub ^ bx1));
                    LDSM4(l4,l5,l6,l7, bL2 + (kub ^ bx2));
                    MMA16816(acc[0][0], ah0.x,ah0.y,ah0.z,ah0.w, h0,h1);
                    MMA16816(acc[0][1], ah0.x,ah0.y,ah0.z,ah0.w, h2,h3);
                    MMA16816(acc[0][2], ah0.x,ah0.y,ah0.z,ah0.w, h4,h5);
                    MMA16816(acc[0][3], ah0.x,ah0.y,ah0.z,ah0.w, h6,h7);
                    MMA16816(acc[0][0], ah0.x,ah0.y,ah0.z,ah0.w, l0,l1);
                    MMA16816(acc[0][1], ah0.x,ah0.y,ah0.z,ah0.w, l2,l3);
                    MMA16816(acc[0][2], ah0.x,ah0.y,ah0.z,ah0.w, l4,l5);
                    MMA16816(acc[0][3], ah0.x,ah0.y,ah0.z,ah0.w, l6,l7);
                    MMA16816(acc[0][0], al0.x,al0.y,al0.z,al0.w, h0,h1);
                    MMA16816(acc[0][1], al0.x,al0.y,al0.z,al0.w, h2,h3);
                    MMA16816(acc[0][2], al0.x,al0.y,al0.z,al0.w, h4,h5);
                    MMA16816(acc[0][3], al0.x,al0.y,al0.z,al0.w, h6,h7);
                    MMA16816(acc[1][0], ah1.x,ah1.y,ah1.z,ah1.w, h0,h1);
                    MMA16816(acc[1][1], ah1.x,ah1.y,ah1.z,ah1.w, h2,h3);
                    MMA16816(acc[1][2], ah1.x,ah1.y,ah1.z,ah1.w, h4,h5);
                    MMA16816(acc[1][3], ah1.x,ah1.y,ah1.z,ah1.w, h6,h7);
                    MMA16816(acc[1][0], ah1.x,ah1.y,ah1.z,ah1.w, l0,l1);
                    MMA16816(acc[1][1], ah1.x,ah1.y,ah1.z,ah1.w, l2,l3);
                    MMA16816(acc[1][2], ah1.x,ah1.y,ah1.z,ah1.w, l4,l5);
                    MMA16816(acc[1][3], ah1.x,ah1.y,ah1.z,ah1.w, l6,l7);
                    MMA16816(acc[1][0], al1.x,al1.y,al1.z,al1.w, h0,h1);
                    MMA16816(acc[1][1], al1.x,al1.y,al1.z,al1.w, h2,h3);
                    MMA16816(acc[1][2], al1.x,al1.y,al1.z,al1.w, h4,h5);
                    MMA16816(acc[1][3], al1.x,al1.y,al1.z,al1.w, h6,h7);
                }
            }
        }
        __syncthreads();   // all IN reads done before S aliases into it

        float* Sbase = (float*)(smem + SM_IN + curbuf*BUF_STRIDE);
        float* Sw = Sbase + ks*4160;
        #pragma unroll
        for (int mt = 0; mt < 2; mt++) {
            #pragma unroll
            for (int j = 0; j < 4; j++) {
                int pc = px_base + 8*j + 2*(lane & 3);
                int mr = co_base + mt*16 + (lane >> 2);
                Sw[pc*65 + mr]           = acc[mt][j][0];
                Sw[(pc+1)*65 + mr]       = acc[mt][j][1];
                Sw[pc*65 + mr + 8]       = acc[mt][j][2];
                Sw[(pc+1)*65 + mr + 8]   = acc[mt][j][3];
            }
        }
        __syncthreads();

        const float* S0 = Sbase;
        const float* S1 = Sbase + 4160;
        if (mode == 0) {
            const int px = tid >> 2, cb = (tid & 3) * 16;
            uint32_t hw[8], lw[8];
            #pragma unroll
            for (int j = 0; j < 8; j++) {
                int i0 = px*65 + cb + 2*j;
                float v0 = fmaxf(S0[i0]     + S1[i0]     + sBias[cb + 2*j],     0.f);
                float v1 = fmaxf(S0[i0 + 1] + S1[i0 + 1] + sBias[cb + 2*j + 1], 0.f);
                __nv_bfloat16 h0 = __float2bfloat16(v0);
                __nv_bfloat16 h1 = __float2bfloat16(v1);
                hw[j] = pack_bits(h0, h1);
                lw[j] = pack_cvt(v0 - __bfloat162float(h0), v1 - __bfloat162float(h1));
            }
            uint16_t* ob = (uint16_t*)outP;
            size_t e = (((size_t)sl*128 + h)*128 + (w0 + px))*64 + cb;
            *(uint4*)(ob + e)     = make_uint4(hw[0], hw[1], hw[2], hw[3]);
            *(uint4*)(ob + e + 8) = make_uint4(hw[4], hw[5], hw[6], hw[7]);
            *(uint4*)(ob + HALF_ELEMS + e)     = make_uint4(lw[0], lw[1], lw[2], lw[3]);
            *(uint4*)(ob + HALF_ELEMS + e + 8) = make_uint4(lw[4], lw[5], lw[6], lw[7]);
        } else {
            const int co = tid >> 2, pb = (tid & 3) * 16;
            const int b_ = sl >> 3, d_ = sl & 7;
            const float bv = sBias[co];
            float* ob = (float*)outP +
                ((size_t)(b_*64 + co)*8 + d_)*16384 + h*128 + w0 + pb;
            #pragma unroll
            for (int q = 0; q < 4; q++) {
                float4 o;
                int i0 = (pb + 4*q)*65 + co;
                o.x = fmaxf(S0[i0]        + S1[i0]        + bv, 0.f);
                o.y = fmaxf(S0[i0 + 65]   + S1[i0 + 65]   + bv, 0.f);
                o.z = fmaxf(S0[i0 + 130]  + S1[i0 + 130]  + bv, 0.f);
                o.w = fmaxf(S0[i0 + 195]  + S1[i0 + 195]  + bv, 0.f);
                *(float4*)(ob + 4*q) = o;
            }
        }
        __syncthreads();   // epilogue done before next stage overwrites S region
        curbuf ^= 1;
    }
}

// ---------------- segment sums ----------------
#define VCH 2048
__global__ __launch_bounds__(256)
void segsum_kernel(const float* __restrict__ x, const int* __restrict__ labels)
{
    __shared__ float sAcc[LL*CC];
    __shared__ float sCnt[LL];
    __shared__ int sLab[VCH];
    const int b = blockIdx.y;
    const int v0 = blockIdx.x * VCH;
    const int tid = threadIdx.x;

    for (int i = tid; i < LL*CC; i += 256) sAcc[i] = 0.f;
    for (int i = tid; i < LL; i += 256) sCnt[i] = 0.f;
    for (int i = tid; i < VCH; i += 256) sLab[i] = labels[(size_t)b*VV + v0 + i];
    __syncthreads();

    for (int i = tid; i < VCH; i += 256) atomicAdd(&sCnt[sLab[i]], 1.f);
    const float* xb = x + (size_t)b*64*VV + v0;
    for (int c = 0; c < 64; c++) {
        const float* xc = xb + (size_t)c*VV;
        for (int i = tid; i < VCH; i += 256)
            atomicAdd(&sAcc[sLab[i]*64 + c], xc[i]);
    }
    __syncthreads();
    for (int i = tid; i < LL*CC; i += 256) atomicAdd(&g_sums[b*LL*CC + i], sAcc[i]);
    for (int i = tid; i < LL; i += 256) atomicAdd(&g_counts[b*LL + i], sCnt[i]);
}

// ---------------- inst features + mask_kernel linear ----------------
__global__ __launch_bounds__(256)
void instfeat_kernel(const float* __restrict__ embed, const float* __restrict__ mk_w,
                     const float* __restrict__ mk_b, float* __restrict__ if_out,
                     int write_if)
{
    __shared__ float sInst[NN*CC];
    __shared__ float sWT[CC*KD];
    const int b = blockIdx.x;
    const int tid = threadIdx.x;

    for (int idx = tid; idx < CC*KD; idx += 256) {
        int kd = idx & 63, c = idx >> 6;
        sWT[c*64 + kd] = mk_w[kd*64 + c];
    }
    for (int idx = tid; idx < 100*CC; idx += 256) {
        int n = idx >> 6, c = idx & 63;
        int l = n + 1;
        float cnt = fmaxf(g_counts[b*LL + l], 1.f);
        sInst[idx] = g_sums[(b*LL + l)*64 + c] / cnt;
    }
    for (int idx = tid; idx < NLM*CC; idx += 256)
        sInst[100*CC + idx] = embed[idx];
    __syncthreads();

    if (write_if)
        for (int idx = tid; idx < NN*CC; idx += 256)
            if_out[(size_t)b*NN*CC + idx] = sInst[idx];

    for (int idx = tid; idx < NN*KD; idx += 256) {
        int n = idx >> 6, kd = idx & 63;
        const float* ip = sInst + n*64;
        float a = mk_b[kd];
        #pragma unroll
        for (int c = 0; c < 64; c++)
            a = fmaf(ip[c], sWT[c*64 + kd], a);
        g_kraw[(size_t)b*NN*KD + idx] = a;
    }
}

// ---------------- BatchNorm1d over (B,N) per KD channel (parallel) ----------------
__global__ __launch_bounds__(256)
void bnk_kernel(const float* __restrict__ gamma, const float* __restrict__ beta,
                float* __restrict__ pk_out, int write_pk)
{
    __shared__ float ssum[256], ssq[256];
    __shared__ float sm[64], si[64], sg[64], sbt[64];
    const int tid = threadIdx.x;
    const int kd = tid & 63, q = tid >> 6;
    float s = 0.f, sq = 0.f;
    for (int i = q; i < BB*NN; i += 4) {
        float v = g_kraw[i*64 + kd];
        s += v; sq += v*v;
    }
    ssum[tid] = s; ssq[tid] = sq;
    __syncthreads();
    if (tid < 64) {
        float S = ssum[tid] + ssum[tid+64] + ssum[tid+128] + ssum[tid+192];
        float Q = ssq[tid] + ssq[tid+64] + ssq[tid+128] + ssq[tid+192];
        float mean = S / (float)(BB*NN);
        float var = Q / (float)(BB*NN) - mean*mean;
        sm[tid] = mean;
        si[tid] = rsqrtf(var + EPSV);
        sg[tid] = gamma[tid];
        sbt[tid] = beta[tid];
    }
    __syncthreads();
    for (int e = tid; e < BB*NN*KD; e += 256) {
        int k2 = e & 63;
        float v = (g_kraw[e] - sm[k2]) * si[k2] * sg[k2] + sbt[k2];
        g_knorm[e] = v;
        if (write_pk) pk_out[e] = v;
    }
}

// ---------------- bmm via mma.sync: masks = knorm[120x64] @ MF[64xV] + stats ------
#define BM_BH 0
#define BM_BL 8192
#define BM_S  16384
#define BM_RS (16384 + 33280)     // 49664
#define BM_RQ (BM_RS + 1024)
#define BMM_SMEM (BM_RQ + 1024)   // 51712

__global__ __launch_bounds__(256)
void bmm_mma_kernel(const float* __restrict__ mf, float* __restrict__ pm)
{
    extern __shared__ char bsm[];
    const uint32_t sb = smem_u32(bsm);
    float* S = (float*)(bsm + BM_S);
    float* rs = (float*)(bsm + BM_RS);
    float* rq = (float*)(bsm + BM_RQ);
    const int b = blockIdx.y;
    const int v0 = blockIdx.x * 64;
    const int tid = threadIdx.x;
    const int wid = tid >> 5, lane = tid & 31;

    {
        const float* mb = mf + ((size_t)(b*64 + 8*wid))*VV + v0;
        #pragma unroll
        for (int it = 0; it < 2; it++) {
            const int px = lane + it*32;
            float x[8];
            #pragma unroll
            for (int kk = 0; kk < 8; kk++)
                x[kk] = mb[(size_t)kk*VV + px];
            uint32_t hw[4], lw[4];
            #pragma unroll
            for (int j = 0; j < 4; j++) {
                float a = x[2*j], c = x[2*j + 1];
                __nv_bfloat16 ha = __float2bfloat16(a);
                __nv_bfloat16 hc = __float2bfloat16(c);
                hw[j] = pack_bits(ha, hc);
                lw[j] = pack_cvt(a - __bfloat162float(ha), c - __bfloat162float(hc));
            }
            uint32_t addr = (uint32_t)(px*128 + ((wid ^ (px & 7)) << 4));
            asm volatile("st.shared.v4.b32 [%0], {%1,%2,%3,%4};"
                :: "r"(sb + BM_BH + addr), "r"(hw[0]), "r"(hw[1]), "r"(hw[2]), "r"(hw[3]) : "memory");
            asm volatile("st.shared.v4.b32 [%0], {%1,%2,%3,%4};"
                :: "r"(sb + BM_BL + addr), "r"(lw[0]), "r"(lw[1]), "r"(lw[2]), "r"(lw[3]) : "memory");
        }
    }
    __syncthreads();

    const int mgrp = wid >> 1;
    const int pxg  = wid & 1;
    const int bn  = (lane & 7) + (lane >> 4) * 8;
    const int bkh = (lane >> 3) & 1;
    const int spx1 = pxg*32 + bn;
    const int spx2 = spx1 + 16;
    const uint32_t bH1 = sb + BM_BH + spx1*128;
    const uint32_t bH2 = sb + BM_BH + spx2*128;
    const uint32_t bL1 = sb + BM_BL + spx1*128;
    const uint32_t bL2 = sb + BM_BL + spx2*128;
    const uint32_t bx1 = (uint32_t)((spx1 & 7) << 4);
    const uint32_t bx2 = (uint32_t)((spx2 & 7) << 4);
    const uint4* khp = g_kfrag + (b*2 + 0)*1024;
    const uint4* klp = g_kfrag + (b*2 + 1)*1024;

    float acc[2][4][4] = {};
    #pragma unroll
    for (int kc = 0; kc < 4; kc++) {
        const uint32_t kub = (uint32_t)(kc*32 + bkh*16);
        uint4 ah0 = khp[kc*256 + (mgrp*2)*32 + lane];
        uint4 ah1 = khp[kc*256 + (mgrp*2 + 1)*32 + lane];
        uint4 al0 = klp[kc*256 + (mgrp*2)*32 + lane];
        uint4 al1 = klp[kc*256 + (mgrp*2 + 1)*32 + lane];
        uint32_t h0,h1,h2,h3, h4,h5,h6,h7;
        LDSM4(h0,h1,h2,h3, bH1 + (kub ^ bx1));
        LDSM4(h4,h5,h6,h7, bH2 + (kub ^ bx2));
        uint32_t l0,l1,l2,l3, l4,l5,l6,l7;
        LDSM4(l0,l1,l2,l3, bL1 + (kub ^ bx1));
        LDSM4(l4,l5,l6,l7, bL2 + (kub ^ bx2));
        MMA16816(acc[0][0], ah0.x,ah0.y,ah0.z,ah0.w, h0,h1);
        MMA16816(acc[0][1], ah0.x,ah0.y,ah0.z,ah0.w, h2,h3);
        MMA16816(acc[0][2], ah0.x,ah0.y,ah0.z,ah0.w, h4,h5);
        MMA16816(acc[0][3], ah0.x,ah0.y,ah0.z,ah0.w, h6,h7);
        MMA16816(acc[0][0], ah0.x,ah0.y,ah0.z,ah0.w, l0,l1);
        MMA16816(acc[0][1], ah0.x,ah0.y,ah0.z,ah0.w, l2,l3);
        MMA16816(acc[0][2], ah0.x,ah0.y,ah0.z,ah0.w, l4,l5);
        MMA16816(acc[0][3], ah0.x,ah0.y,ah0.z,ah0.w, l6,l7);
        MMA16816(acc[0][0], al0.x,al0.y,al0.z,al0.w, h0,h1);
        MMA16816(acc[0][1], al0.x,al0.y,al0.z,al0.w, h2,h3);
        MMA16816(acc[0][2], al0.x,al0.y,al0.z,al0.w, h4,h5);
        MMA16816(acc[0][3], al0.x,al0.y,al0.z,al0.w, h6,h7);
        MMA16816(acc[1][0], ah1.x,ah1.y,ah1.z,ah1.w, h0,h1);
        MMA16816(acc[1][1], ah1.x,ah1.y,ah1.z,ah1.w, h2,h3);
        MMA16816(acc[1][2], ah1.x,ah1.y,ah1.z,ah1.w, h4,h5);
        MMA16816(acc[1][3], ah1.x,ah1.y,ah1.z,ah1.w, h6,h7);
        MMA16816(acc[1][0], ah1.x,ah1.y,ah1.z,ah1.w, l0,l1);
        MMA16816(acc[1][1], ah1.x,ah1.y,ah1.z,ah1.w, l2,l3);
        MMA16816(acc[1][2], ah1.x,ah1.y,ah1.z,ah1.w, l4,l5);
        MMA16816(acc[1][3], ah1.x,ah1.y,ah1.z,ah1.w, l6,l7);
        MMA16816(acc[1][0], al1.x,al1.y,al1.z,al1.w, h0,h1);
        MMA16816(acc[1][1], al1.x,al1.y,al1.z,al1.w, h2,h3);
        MMA16816(acc[1][2], al1.x,al1.y,al1.z,al1.w, h4,h5);
        MMA16816(acc[1][3], al1.x,al1.y,al1.z,al1.w, h6,h7);
    }

    #pragma unroll
    for (int mt = 0; mt < 2; mt++) {
        #pragma unroll
        for (int j = 0; j < 4; j++) {
            int pc = pxg*32 + 8*j + 2*(lane & 3);
            int mr = mgrp*32 + mt*16 + (lane >> 2);
            S[mr*65 + pc]           = acc[mt][j][0];
            S[mr*65 + pc + 1]       = acc[mt][j][1];
            S[(mr+8)*65 + pc]       = acc[mt][j][2];
            S[(mr+8)*65 + pc + 1]   = acc[mt][j][3];
        }
    }
    __syncthreads();

    float psum = 0.f, psq = 0.f;
    float* po = pm + (size_t)b*NN*VV + v0;
    for (int idx = tid; idx < NN*64; idx += 256) {
        int n = idx >> 6, px = idx & 63;
        float a = S[n*65 + px];
        po[(size_t)n*VV + px] = a;
        psum += a; psq += a*a;
    }
    rs[tid] = psum; rq[tid] = psq;
    __syncthreads();
    for (int s2 = 128; s2 > 0; s2 >>= 1) {
        if (tid < s2) { rs[tid] += rs[tid+s2]; rq[tid] += rq[tid+s2]; }
        __syncthreads();
    }
    if (tid == 0) {
        atomicAdd(&g_psum, (double)rs[0]);
        atomicAdd(&g_psumsq, (double)rq[0]);
    }
}

// ---------------- global BN over pred_masks ----------------
__global__ void norm_masks_kernel(float* __restrict__ pm,
                                  const float* __restrict__ gam,
                                  const float* __restrict__ bet)
{
    const double N = (double)PM_ELEMS;
    double mean = g_psum / N;
    double var = g_psumsq / N - mean*mean;
    float inv = (float)(1.0 / sqrt(var + (double)EPSV));
    float g = gam[0] * inv;
    float m = (float)mean;
    float be = bet[0];
    float4* p = (float4*)pm;
    const int n4 = PM_ELEMS / 4;
    for (int i = blockIdx.x*blockDim.x + threadIdx.x; i < n4; i += gridDim.x*blockDim.x) {
        float4 v = p[i];
        v.x = (v.x - m)*g + be;
        v.y = (v.y - m)*g + be;
        v.z = (v.z - m)*g + be;
        v.w = (v.w - m)*g + be;
        p[i] = v;
    }
}

// ---------------- launch ----------------
extern "C" void kernel_launch(void* const* d_in, const int* in_sizes, int n_in,
                              void* d_out, int out_size)
{
    const float* features      = (const float*)d_in[0];
    const float* mask_features = (const float*)d_in[1];
    const float* conv_w        = (const float*)d_in[2];
    const float* conv_b        = (const float*)d_in[3];
    const float* embed         = (const float*)d_in[4];
    const float* mk_w          = (const float*)d_in[5];
    const float* mk_b          = (const float*)d_in[6];
    const float* nk_gamma      = (const float*)d_in[7];
    const float* nk_beta       = (const float*)d_in[8];
    const float* nl_gamma      = (const float*)d_in[9];
    const float* nl_beta       = (const float*)d_in[10];
    const int*   init_masks    = (const int*)d_in[11];
    float* out = (float*)d_out;

    float *bufA = nullptr, *bufB = nullptr;
    uint4 *wfragHi = nullptr, *wfragLo = nullptr;
    cudaGetSymbolAddress((void**)&bufA, g_bufA);
    cudaGetSymbolAddress((void**)&bufB, g_bufB);
    cudaGetSymbolAddress((void**)&wfragHi, g_wfragHi);
    cudaGetSymbolAddress((void**)&wfragLo, g_wfragLo);
    uint16_t* hA = (uint16_t*)bufA;
    uint16_t* hB = (uint16_t*)bufB;

    int full = (out_size >= OUT_FULL) ? 1 : 0;
    int masks_only = (!full && out_size >= PM_ELEMS) ? 1 : 0;

    float* xout  = full ? out : bufB;
    float* ifout = full ? (out + X_ELEMS) : out;
    float* pmout = full ? (out + X_ELEMS + IF_ELEMS) : (masks_only ? out : bufB);
    float* pkout = full ? (out + X_ELEMS + IF_ELEMS + PM_ELEMS) : out;

    static int attr_done = 0;
    if (!attr_done) {
        cudaFuncSetAttribute(conv_mma_kernel,
                             cudaFuncAttributeMaxDynamicSharedMemorySize, CONV_SMEM);
        cudaFuncSetAttribute(bmm_mma_kernel,
                             cudaFuncAttributeMaxDynamicSharedMemorySize, BMM_SMEM);
        attr_done = 1;
    }

    init_zero_kernel<<<1, 256>>>();
    wfrag_kernel<<<72, 256>>>(conv_w);
    trans_kernel<<<2048, 256>>>(features, hB);

    conv_mma_kernel<<<GRIDC, 256, CONV_SMEM>>>(hB, hA,   wfragHi + 0*4608, wfragLo + 0*4608, conv_b + 0,   0);
    conv_mma_kernel<<<GRIDC, 256, CONV_SMEM>>>(hA, hB,   wfragHi + 1*4608, wfragLo + 1*4608, conv_b + 64,  0);
    conv_mma_kernel<<<GRIDC, 256, CONV_SMEM>>>(hB, hA,   wfragHi + 2*4608, wfragLo + 2*4608, conv_b + 128, 0);
    conv_mma_kernel<<<GRIDC, 256, CONV_SMEM>>>(hA, xout, wfragHi + 3*4608, wfragLo + 3*4608, conv_b + 192, 1);

    segsum_kernel<<<dim3(VV/VCH, BB), 256>>>(xout, init_masks);
    instfeat_kernel<<<BB, 256>>>(embed, mk_w, mk_b, ifout, full);
    bnk_kernel<<<1, 256>>>(nk_gamma, nk_beta, pkout, full);

    if (full || masks_only) {
        kfrag_kernel<<<16, 256>>>();
        bmm_mma_kernel<<<dim3(VV/64, BB), 256, BMM_SMEM>>>(mask_features, pmout);
        norm_masks_kernel<<<4096, 256>>>(pmout, nl_gamma, nl_beta);
    }
}

// round 17
// speedup vs baseline: 1.2479x; 1.0003x over previous
#include <cuda_runtime.h>
#include <cuda_bf16.h>
#include <math.h>
#include <stdint.h>

// Problem constants
#define BB 2
#define CC 64
#define DD 8
#define HH 128
#define WW 128
#define VV (DD*HH*WW)          // 131072
#define LL 101
#define KD 64
#define NLM 20
#define NN (100 + NLM)         // 120
#define EPSV 1e-3f

#define X_ELEMS   (BB*CC*VV)          // 16777216
#define IF_ELEMS  (BB*NN*CC)
#define PM_ELEMS  (BB*NN*VV)
#define PK_ELEMS  (BB*NN*KD)
#define OUT_FULL  (X_ELEMS + IF_ELEMS + PM_ELEMS + PK_ELEMS)

#define HALF_ELEMS 16777216           // bf16 elems per (hi|lo) half of a scratch buffer

// ---------------- device scratch ----------------
__device__ float g_bufA[X_ELEMS];     // Hi bf16 [0..16M) + Lo bf16 [16M..32M)
__device__ float g_bufB[X_ELEMS];
__device__ uint4 g_wfragHi[4*9*4*4*32];   // Whi in mma-A fragment order
__device__ uint4 g_wfragLo[4*9*4*4*32];   // Wlo in mma-A fragment order
__device__ uint4 g_kfrag[4096];           // knorm frags: [b][sv][kc][cogrp][lane]
__device__ float g_sums[BB*LL*CC];
__device__ float g_counts[BB*LL];
__device__ float g_kraw[BB*NN*KD];
__device__ float g_knorm[BB*NN*KD];
__device__ double g_psum;
__device__ double g_psumsq;
__device__ float g_scaleS;
__device__ float g_shiftS;

// ================= helpers =================
typedef unsigned long long u64t;
__device__ __forceinline__ uint32_t smem_u32(const void* p) {
    uint32_t a;
    asm("{ .reg .u64 t; cvta.to.shared.u64 t, %1; cvt.u32.u64 %0, t; }"
        : "=r"(a) : "l"(p));
    return a;
}
__device__ __forceinline__ uint32_t pack_bits(__nv_bfloat16 lo, __nv_bfloat16 hi) {
    return (uint32_t)__bfloat16_as_ushort(lo) | ((uint32_t)__bfloat16_as_ushort(hi) << 16);
}
__device__ __forceinline__ uint32_t pack_cvt(float lo, float hi) {
    uint32_t r;
    asm("cvt.rn.bf16x2.f32 %0, %1, %2;" : "=r"(r) : "f"(hi), "f"(lo));
    return r;
}
__device__ __forceinline__ float bf_round(float x) {
    return __bfloat162float(__float2bfloat16(x));
}

#define LDSM4(r0,r1,r2,r3, addr) \
    asm volatile("ldmatrix.sync.aligned.m8n8.x4.shared.b16 {%0,%1,%2,%3}, [%4];" \
        : "=r"(r0),"=r"(r1),"=r"(r2),"=r"(r3) : "r"(addr))

#define MMA16816(d, a0,a1,a2,a3, b0,b1) \
    asm volatile("mma.sync.aligned.m16n8k16.row.col.f32.bf16.bf16.f32 " \
        "{%0,%1,%2,%3}, {%4,%5,%6,%7}, {%8,%9}, {%0,%1,%2,%3};" \
        : "+f"((d)[0]), "+f"((d)[1]), "+f"((d)[2]), "+f"((d)[3]) \
        : "r"(a0),"r"(a1),"r"(a2),"r"(a3), "r"(b0),"r"(b1))

#define CP_ASYNC16(dst, src, n) \
    asm volatile("cp.async.cg.shared.global [%0], [%1], 16, %2;" \
        :: "r"(dst), "l"(src), "r"(n) : "memory")
#define CP_COMMIT() asm volatile("cp.async.commit_group;" ::: "memory")
#define CP_WAIT0()  asm volatile("cp.async.wait_group 0;" ::: "memory")
#define CP_WAIT1()  asm volatile("cp.async.wait_group 1;" ::: "memory")

// ---------------- init ----------------
__global__ void init_zero_kernel() {
    int tid = threadIdx.x;
    if (tid == 0) { g_psum = 0.0; g_psumsq = 0.0; }
    for (int i = tid; i < BB*LL*CC; i += 256) g_sums[i] = 0.f;
    for (int i = tid; i < BB*LL; i += 256) g_counts[i] = 0.f;
}

// ---------------- W -> mma A-fragment order, hi+lo tables (all 4 layers) ----------------
__global__ void wfrag_kernel(const float* __restrict__ w) {
    int idx = blockIdx.x * 256 + threadIdx.x;
    if (idx >= 18432) return;
    int lane = idx & 31;
    int r = idx >> 5;
    int cogrp = r & 3; r >>= 2;
    int kc = r & 3; r >>= 2;
    int tap = r % 9; int l = r / 9;
    int row = cogrp*16 + (lane >> 2);
    int c0 = kc*16 + (lane & 3)*2;
    float v[8];
    v[0] = w[((size_t)(l*64 + row)*64     + c0)*9 + tap];
    v[1] = w[((size_t)(l*64 + row)*64     + c0 + 1)*9 + tap];
    v[2] = w[((size_t)(l*64 + row + 8)*64 + c0)*9 + tap];
    v[3] = w[((size_t)(l*64 + row + 8)*64 + c0 + 1)*9 + tap];
    v[4] = w[((size_t)(l*64 + row)*64     + c0 + 8)*9 + tap];
    v[5] = w[((size_t)(l*64 + row)*64     + c0 + 9)*9 + tap];
    v[6] = w[((size_t)(l*64 + row + 8)*64 + c0 + 8)*9 + tap];
    v[7] = w[((size_t)(l*64 + row + 8)*64 + c0 + 9)*9 + tap];
    uint4 hi, lo;
    hi.x = pack_bits(__float2bfloat16(v[0]), __float2bfloat16(v[1]));
    hi.y = pack_bits(__float2bfloat16(v[2]), __float2bfloat16(v[3]));
    hi.z = pack_bits(__float2bfloat16(v[4]), __float2bfloat16(v[5]));
    hi.w = pack_bits(__float2bfloat16(v[6]), __float2bfloat16(v[7]));
    lo.x = pack_cvt(v[0] - bf_round(v[0]), v[1] - bf_round(v[1]));
    lo.y = pack_cvt(v[2] - bf_round(v[2]), v[3] - bf_round(v[3]));
    lo.z = pack_cvt(v[4] - bf_round(v[4]), v[5] - bf_round(v[5]));
    lo.w = pack_cvt(v[6] - bf_round(v[6]), v[7] - bf_round(v[7]));
    int off = ((l*9 + tap)*4 + kc)*128 + cogrp*32 + lane;
    g_wfragHi[off] = hi;
    g_wfragLo[off] = lo;
}

// ---------------- knorm -> mma A-fragment order, hi+lo (both batches) ----------------
__global__ void kfrag_kernel() {
    int idx = blockIdx.x * 256 + threadIdx.x;
    if (idx >= 4096) return;
    int lane = idx & 31;
    int r = idx >> 5;
    int cogrp = r & 7; r >>= 3;
    int kc = r & 3; r >>= 2;
    int sv = r & 1; int b = r >> 1;
    int row = cogrp*16 + (lane >> 2);
    int c0 = kc*16 + (lane & 3)*2;
    #define KV(rr, cc) ((rr) < NN ? g_knorm[((size_t)b*NN + (rr))*64 + (cc)] : 0.f)
    float v[8];
    v[0] = KV(row, c0);     v[1] = KV(row, c0+1);
    v[2] = KV(row+8, c0);   v[3] = KV(row+8, c0+1);
    v[4] = KV(row, c0+8);   v[5] = KV(row, c0+9);
    v[6] = KV(row+8, c0+8); v[7] = KV(row+8, c0+9);
    #undef KV
    uint4 o;
    if (sv == 0) {
        o.x = pack_bits(__float2bfloat16(v[0]), __float2bfloat16(v[1]));
        o.y = pack_bits(__float2bfloat16(v[2]), __float2bfloat16(v[3]));
        o.z = pack_bits(__float2bfloat16(v[4]), __float2bfloat16(v[5]));
        o.w = pack_bits(__float2bfloat16(v[6]), __float2bfloat16(v[7]));
    } else {
        o.x = pack_cvt(v[0] - bf_round(v[0]), v[1] - bf_round(v[1]));
        o.y = pack_cvt(v[2] - bf_round(v[2]), v[3] - bf_round(v[3]));
        o.z = pack_cvt(v[4] - bf_round(v[4]), v[5] - bf_round(v[5]));
        o.w = pack_cvt(v[6] - bf_round(v[6]), v[7] - bf_round(v[7]));
    }
    g_kfrag[((b*2 + sv)*4 + kc)*256 + cogrp*32 + lane] = o;
}

// ---------------- features (ch-major fp32) -> pixel-major bf16 hi/lo ----------------
__global__ __launch_bounds__(256)
void trans_kernel(const float* __restrict__ in, uint16_t* __restrict__ outHi) {
    __shared__ float s[64][129];
    const int blk = blockIdx.x;
    const int sl = blk >> 7;
    const int h  = blk & 127;
    const int b = sl >> 3, d = sl & 7;
    const int tid = threadIdx.x;
    for (int i = tid; i < 8192; i += 256) {
        int c = i >> 7, w = i & 127;
        s[c][w] = in[((size_t)(b*64 + c)*8 + d)*16384 + h*128 + w];
    }
    __syncthreads();
    for (int i = tid; i < 1024; i += 256) {
        int w = i >> 3, ch = i & 7;
        uint32_t hw[4], lw[4];
        #pragma unroll
        for (int j = 0; j < 4; j++) {
            float v0 = s[ch*8 + 2*j][w];
            float v1 = s[ch*8 + 2*j + 1][w];
            __nv_bfloat16 h0 = __float2bfloat16(v0);
            __nv_bfloat16 h1 = __float2bfloat16(v1);
            hw[j] = pack_bits(h0, h1);
            lw[j] = pack_cvt(v0 - __bfloat162float(h0), v1 - __bfloat162float(h1));
        }
        size_t e = (((size_t)sl*128 + h)*128 + w)*64 + ch*8;
        *(uint4*)(outHi + e) = make_uint4(hw[0], hw[1], hw[2], hw[3]);
        *(uint4*)(outHi + HALF_ELEMS + e) = make_uint4(lw[0], lw[1], lw[2], lw[3]);
    }
}

// ================= mma.sync conv: 2 CTAs/SM, A from gmem fragment tables ==========
#define SM_IN    0            // 2 x 50688
#define SM_BIAS  101376
#define CONV_SMEM 101632
#define IN_ROW   8448         // 66 px * 128 B
#define BUF_STRIDE 50688
#define GRIDC 296

__global__ __launch_bounds__(256, 2)
void conv_mma_kernel(const uint16_t* __restrict__ inBuf,
                     void* __restrict__ outP,
                     const uint4* __restrict__ wfragHi,
                     const uint4* __restrict__ wfragLo,
                     const float* __restrict__ bias,
                     int mode)
{
    extern __shared__ char smem[];
    const uint32_t sb = smem_u32(smem);
    float* sBias = (float*)(smem + SM_BIAS);
    const int tid = threadIdx.x;
    const int wid = tid >> 5, lane = tid & 31;

    if (tid < 64) sBias[tid] = bias[tid];
    __syncthreads();

    const int ks      = wid >> 2;
    const int cg2     = (wid >> 1) & 1;
    const int co_base = cg2 * 32;
    const int px_base = (wid & 1) * 32;
    const int bn  = (lane & 7) + (lane >> 4) * 8;
    const int bkh = (lane >> 3) & 1;

    uint32_t meta[13];
    #pragma unroll
    for (int j = 0; j < 13; j++) {
        int i = tid + j*256;
        if (i < 3168) {
            int bsel = (i >= 1584) ? 1 : 0;
            int r = i - bsel*1584;
            int ky = r / 528; int rem = r - ky*528;
            int px = rem >> 3; int ch = rem & 7;
            uint32_t dsto = (uint32_t)(bsel*25344 + ky*IN_ROW + px*128 +
                                       ((ch ^ (px & 7)) << 4));
            meta[j] = dsto | ((uint32_t)ky << 16) | ((uint32_t)px << 18) |
                      ((uint32_t)ch << 25) | ((uint32_t)bsel << 28) | (1u << 31);
        } else meta[j] = 0;
    }

    auto stage_tile = [&](int buf, int t) {
        const int sl = t >> 8;
        const int h  = (t >> 1) & 127;
        const int w0 = (t & 1) << 6;
        const uint32_t dstBase = sb + SM_IN + buf*BUF_STRIDE;
        const uint16_t* base = inBuf + (size_t)sl * 1048576;
        #pragma unroll
        for (int j = 0; j < 13; j++) {
            uint32_t m = meta[j];
            if (m & (1u << 31)) {
                int ky = (m >> 16) & 3;
                int px = (m >> 18) & 127;
                int ch = (m >> 25) & 7;
                int bsel = (m >> 28) & 1;
                int gh = h + ky - 1, gw = w0 + px - 1;
                uint32_t ok = (((unsigned)gh < 128u) & ((unsigned)gw < 128u)) ? 1u : 0u;
                int cgh = ok ? gh : 0, cgw = ok ? gw : 0;
                const uint16_t* src = base + (size_t)bsel*HALF_ELEMS +
                        (((uint32_t)(cgh*128 + cgw)) << 6) + (ch << 3);
                CP_ASYNC16(dstBase + (m & 0xFFFFu), src, ok ? 16u : 0u);
            }
        }
        CP_COMMIT();
    };

    int t = blockIdx.x;
    int curbuf = 0;

    if ((blockIdx.x & 1) && t < 4096) {
        stage_tile(0, t);
        CP_WAIT0();
    }
    if (t < 4096) stage_tile(0, t);

    for (; t < 4096; t += GRIDC) {
        const int sl = t >> 8;
        const int h  = (t >> 1) & 127;
        const int w0 = (t & 1) << 6;
        const int nt = t + GRIDC;

        if (nt < 4096) { stage_tile(curbuf ^ 1, nt); CP_WAIT1(); }
        else           { CP_WAIT0(); }
        __syncthreads();

        const uint32_t inHi = sb + SM_IN + curbuf*BUF_STRIDE;
        const uint32_t inLo = inHi + 25344;

        float acc[2][4][4] = {};
        #pragma unroll
        for (int ky = 0; ky < 3; ky++) {
            const uint32_t bHrow = inHi + ky*IN_ROW;
            const uint32_t bLrow = inLo + ky*IN_ROW;
            #pragma unroll
            for (int kx = 0; kx < 3; kx++) {
                const int tap = ky*3 + kx;
                const int spx1 = px_base + bn + kx;
                const int spx2 = spx1 + 16;
                const uint32_t bH1 = bHrow + spx1*128;
                const uint32_t bH2 = bHrow + spx2*128;
                const uint32_t bL1 = bLrow + spx1*128;
                const uint32_t bL2 = bLrow + spx2*128;
                const uint32_t bx1 = (uint32_t)((spx1 & 7) << 4);
                const uint32_t bx2 = (uint32_t)((spx2 & 7) << 4);
                const uint4* whp = wfragHi + (tap*4)*128 + lane;
                const uint4* wlp = wfragLo + (tap*4)*128 + lane;
                #pragma unroll
                for (int kc2 = 0; kc2 < 2; kc2++) {
                    const int kc = ks*2 + kc2;
                    const uint32_t kub = (uint32_t)(kc*32 + bkh*16);
                    uint4 ah0 = whp[kc*128 + (2*cg2)*32];
                    uint4 ah1 = whp[kc*128 + (2*cg2 + 1)*32];
                    uint4 al0 = wlp[kc*128 + (2*cg2)*32];
                    uint4 al1 = wlp[kc*128 + (2*cg2 + 1)*32];
                    uint32_t h0,h1,h2,h3, h4,h5,h6,h7;
                    LDSM4(h0,h1,h2,h3, bH1 + (kub ^ bx1));
                    LDSM4(h4,h5,h6,h7, bH2 + (kub ^ bx2));
                    uint32_t l0,l1,l2,l3, l4,l5,l6,l7;
                    LDSM4(l0,l1,l2,l3, bL1 + (kub ^ bx1));
                    LDSM4(l4,l5,l6,l7, bL2 + (kub ^ bx2));
                    MMA16816(acc[0][0], ah0.x,ah0.y,ah0.z,ah0.w, h0,h1);
                    MMA16816(acc[0][1], ah0.x,ah0.y,ah0.z,ah0.w, h2,h3);
                    MMA16816(acc[0][2], ah0.x,ah0.y,ah0.z,ah0.w, h4,h5);
                    MMA16816(acc[0][3], ah0.x,ah0.y,ah0.z,ah0.w, h6,h7);
                    MMA16816(acc[0][0], ah0.x,ah0.y,ah0.z,ah0.w, l0,l1);
                    MMA16816(acc[0][1], ah0.x,ah0.y,ah0.z,ah0.w, l2,l3);
                    MMA16816(acc[0][2], ah0.x,ah0.y,ah0.z,ah0.w, l4,l5);
                    MMA16816(acc[0][3], ah0.x,ah0.y,ah0.z,ah0.w, l6,l7);
                    MMA16816(acc[0][0], al0.x,al0.y,al0.z,al0.w, h0,h1);
                    MMA16816(acc[0][1], al0.x,al0.y,al0.z,al0.w, h2,h3);
                    MMA16816(acc[0][2], al0.x,al0.y,al0.z,al0.w, h4,h5);
                    MMA16816(acc[0][3], al0.x,al0.y,al0.z,al0.w, h6,h7);
                    MMA16816(acc[1][0], ah1.x,ah1.y,ah1.z,ah1.w, h0,h1);
                    MMA16816(acc[1][1], ah1.x,ah1.y,ah1.z,ah1.w, h2,h3);
                    MMA16816(acc[1][2], ah1.x,ah1.y,ah1.z,ah1.w, h4,h5);
                    MMA16816(acc[1][3], ah1.x,ah1.y,ah1.z,ah1.w, h6,h7);
                    MMA16816(acc[1][0], ah1.x,ah1.y,ah1.z,ah1.w, l0,l1);
                    MMA16816(acc[1][1], ah1.x,ah1.y,ah1.z,ah1.w, l2,l3);
                    MMA16816(acc[1][2], ah1.x,ah1.y,ah1.z,ah1.w, l4,l5);
                    MMA16816(acc[1][3], ah1.x,ah1.y,ah1.z,ah1.w, l6,l7);
                    MMA16816(acc[1][0], al1.x,al1.y,al1.z,al1.w, h0,h1);
                    MMA16816(acc[1][1], al1.x,al1.y,al1.z,al1.w, h2,h3);
                    MMA16816(acc[1][2], al1.x,al1.y,al1.z,al1.w, h4,h5);
                    MMA16816(acc[1][3], al1.x,al1.y,al1.z,al1.w, h6,h7);
                }
            }
        }
        __syncthreads();

        float* Sbase = (float*)(smem + SM_IN + curbuf*BUF_STRIDE);
        float* Sw = Sbase + ks*4160;
        #pragma unroll
        for (int mt = 0; mt < 2; mt++) {
            #pragma unroll
            for (int j = 0; j < 4; j++) {
                int pc = px_base + 8*j + 2*(lane & 3);
                int mr = co_base + mt*16 + (lane >> 2);
                Sw[pc*65 + mr]           = acc[mt][j][0];
                Sw[(pc+1)*65 + mr]       = acc[mt][j][1];
                Sw[pc*65 + mr + 8]       = acc[mt][j][2];
                Sw[(pc+1)*65 + mr + 8]   = acc[mt][j][3];
            }
        }
        __syncthreads();

        const float* S0 = Sbase;
        const float* S1 = Sbase + 4160;
        if (mode == 0) {
            const int px = tid >> 2, cb = (tid & 3) * 16;
            uint32_t hw[8], lw[8];
            #pragma unroll
            for (int j = 0; j < 8; j++) {
                int i0 = px*65 + cb + 2*j;
                float v0 = fmaxf(S0[i0]     + S1[i0]     + sBias[cb + 2*j],     0.f);
                float v1 = fmaxf(S0[i0 + 1] + S1[i0 + 1] + sBias[cb + 2*j + 1], 0.f);
                __nv_bfloat16 h0 = __float2bfloat16(v0);
                __nv_bfloat16 h1 = __float2bfloat16(v1);
                hw[j] = pack_bits(h0, h1);
                lw[j] = pack_cvt(v0 - __bfloat162float(h0), v1 - __bfloat162float(h1));
            }
            uint16_t* ob = (uint16_t*)outP;
            size_t e = (((size_t)sl*128 + h)*128 + (w0 + px))*64 + cb;
            *(uint4*)(ob + e)     = make_uint4(hw[0], hw[1], hw[2], hw[3]);
            *(uint4*)(ob + e + 8) = make_uint4(hw[4], hw[5], hw[6], hw[7]);
            *(uint4*)(ob + HALF_ELEMS + e)     = make_uint4(lw[0], lw[1], lw[2], lw[3]);
            *(uint4*)(ob + HALF_ELEMS + e + 8) = make_uint4(lw[4], lw[5], lw[6], lw[7]);
        } else {
            const int co = tid >> 2, pb = (tid & 3) * 16;
            const int b_ = sl >> 3, d_ = sl & 7;
            const float bv = sBias[co];
            float* ob = (float*)outP +
                ((size_t)(b_*64 + co)*8 + d_)*16384 + h*128 + w0 + pb;
            #pragma unroll
            for (int q = 0; q < 4; q++) {
                float4 o;
                int i0 = (pb + 4*q)*65 + co;
                o.x = fmaxf(S0[i0]        + S1[i0]        + bv, 0.f);
                o.y = fmaxf(S0[i0 + 65]   + S1[i0 + 65]   + bv, 0.f);
                o.z = fmaxf(S0[i0 + 130]  + S1[i0 + 130]  + bv, 0.f);
                o.w = fmaxf(S0[i0 + 195]  + S1[i0 + 195]  + bv, 0.f);
                *(float4*)(ob + 4*q) = o;
            }
        }
        __syncthreads();
        curbuf ^= 1;
    }
}

// ---------------- segment sums ----------------
#define VCH 2048
__global__ __launch_bounds__(256)
void segsum_kernel(const float* __restrict__ x, const int* __restrict__ labels)
{
    __shared__ float sAcc[LL*CC];
    __shared__ float sCnt[LL];
    __shared__ int sLab[VCH];
    const int b = blockIdx.y;
    const int v0 = blockIdx.x * VCH;
    const int tid = threadIdx.x;

    for (int i = tid; i < LL*CC; i += 256) sAcc[i] = 0.f;
    for (int i = tid; i < LL; i += 256) sCnt[i] = 0.f;
    for (int i = tid; i < VCH; i += 256) sLab[i] = labels[(size_t)b*VV + v0 + i];
    __syncthreads();

    for (int i = tid; i < VCH; i += 256) atomicAdd(&sCnt[sLab[i]], 1.f);
    const float* xb = x + (size_t)b*64*VV + v0;
    for (int c = 0; c < 64; c++) {
        const float* xc = xb + (size_t)c*VV;
        for (int i = tid; i < VCH; i += 256)
            atomicAdd(&sAcc[sLab[i]*64 + c], xc[i]);
    }
    __syncthreads();
    for (int i = tid; i < LL*CC; i += 256) atomicAdd(&g_sums[b*LL*CC + i], sAcc[i]);
    for (int i = tid; i < LL; i += 256) atomicAdd(&g_counts[b*LL + i], sCnt[i]);
}

// ---------------- inst features + mask_kernel linear ----------------
__global__ __launch_bounds__(256)
void instfeat_kernel(const float* __restrict__ embed, const float* __restrict__ mk_w,
                     const float* __restrict__ mk_b, float* __restrict__ if_out,
                     int write_if)
{
    __shared__ float sInst[NN*CC];
    __shared__ float sWT[CC*KD];
    const int b = blockIdx.x;
    const int tid = threadIdx.x;

    for (int idx = tid; idx < CC*KD; idx += 256) {
        int kd = idx & 63, c = idx >> 6;
        sWT[c*64 + kd] = mk_w[kd*64 + c];
    }
    for (int idx = tid; idx < 100*CC; idx += 256) {
        int n = idx >> 6, c = idx & 63;
        int l = n + 1;
        float cnt = fmaxf(g_counts[b*LL + l], 1.f);
        sInst[idx] = g_sums[(b*LL + l)*64 + c] / cnt;
    }
    for (int idx = tid; idx < NLM*CC; idx += 256)
        sInst[100*CC + idx] = embed[idx];
    __syncthreads();

    if (write_if)
        for (int idx = tid; idx < NN*CC; idx += 256)
            if_out[(size_t)b*NN*CC + idx] = sInst[idx];

    for (int idx = tid; idx < NN*KD; idx += 256) {
        int n = idx >> 6, kd = idx & 63;
        const float* ip = sInst + n*64;
        float a = mk_b[kd];
        #pragma unroll
        for (int c = 0; c < 64; c++)
            a = fmaf(ip[c], sWT[c*64 + kd], a);
        g_kraw[(size_t)b*NN*KD + idx] = a;
    }
}

// ---------------- BatchNorm1d over (B,N) per KD channel (parallel) ----------------
__global__ __launch_bounds__(256)
void bnk_kernel(const float* __restrict__ gamma, const float* __restrict__ beta,
                float* __restrict__ pk_out, int write_pk)
{
    __shared__ float ssum[256], ssq[256];
    __shared__ float sm[64], si[64], sg[64], sbt[64];
    const int tid = threadIdx.x;
    const int kd = tid & 63, q = tid >> 6;
    float s = 0.f, sq = 0.f;
    for (int i = q; i < BB*NN; i += 4) {
        float v = g_kraw[i*64 + kd];
        s += v; sq += v*v;
    }
    ssum[tid] = s; ssq[tid] = sq;
    __syncthreads();
    if (tid < 64) {
        float S = ssum[tid] + ssum[tid+64] + ssum[tid+128] + ssum[tid+192];
        float Q = ssq[tid] + ssq[tid+64] + ssq[tid+128] + ssq[tid+192];
        float mean = S / (float)(BB*NN);
        float var = Q / (float)(BB*NN) - mean*mean;
        sm[tid] = mean;
        si[tid] = rsqrtf(var + EPSV);
        sg[tid] = gamma[tid];
        sbt[tid] = beta[tid];
    }
    __syncthreads();
    for (int e = tid; e < BB*NN*KD; e += 256) {
        int k2 = e & 63;
        float v = (g_kraw[e] - sm[k2]) * si[k2] * sg[k2] + sbt[k2];
        g_knorm[e] = v;
        if (write_pk) pk_out[e] = v;
    }
}

// ========== bmm MMA core (shared by stats and write passes) ==========
#define BM_BH 0
#define BM_BL 8192
#define BM_S  16384
#define BM_RS (16384 + 33280)     // 49664
#define BM_RQ (BM_RS + 1024)
#define BMM_SMEM (BM_RQ + 1024)   // 51712

__device__ __forceinline__ void bmm_core(const float* __restrict__ mf,
                                         uint32_t sb, int b, int v0,
                                         int tid, int wid, int lane,
                                         float acc[2][4][4])
{
    {
        const float* mb = mf + ((size_t)(b*64 + 8*wid))*VV + v0;
        #pragma unroll
        for (int it = 0; it < 2; it++) {
            const int px = lane + it*32;
            float x[8];
            #pragma unroll
            for (int kk = 0; kk < 8; kk++)
                x[kk] = mb[(size_t)kk*VV + px];
            uint32_t hw[4], lw[4];
            #pragma unroll
            for (int j = 0; j < 4; j++) {
                float a = x[2*j], c = x[2*j + 1];
                __nv_bfloat16 ha = __float2bfloat16(a);
                __nv_bfloat16 hc = __float2bfloat16(c);
                hw[j] = pack_bits(ha, hc);
                lw[j] = pack_cvt(a - __bfloat162float(ha), c - __bfloat162float(hc));
            }
            uint32_t addr = (uint32_t)(px*128 + ((wid ^ (px & 7)) << 4));
            asm volatile("st.shared.v4.b32 [%0], {%1,%2,%3,%4};"
                :: "r"(sb + BM_BH + addr), "r"(hw[0]), "r"(hw[1]), "r"(hw[2]), "r"(hw[3]) : "memory");
            asm volatile("st.shared.v4.b32 [%0], {%1,%2,%3,%4};"
                :: "r"(sb + BM_BL + addr), "r"(lw[0]), "r"(lw[1]), "r"(lw[2]), "r"(lw[3]) : "memory");
        }
    }
    __syncthreads();

    const int mgrp = wid >> 1;
    const int pxg  = wid & 1;
    const int bn  = (lane & 7) + (lane >> 4) * 8;
    const int bkh = (lane >> 3) & 1;
    const int spx1 = pxg*32 + bn;
    const int spx2 = spx1 + 16;
    const uint32_t bH1 = sb + BM_BH + spx1*128;
    const uint32_t bH2 = sb + BM_BH + spx2*128;
    const uint32_t bL1 = sb + BM_BL + spx1*128;
    const uint32_t bL2 = sb + BM_BL + spx2*128;
    const uint32_t bx1 = (uint32_t)((spx1 & 7) << 4);
    const uint32_t bx2 = (uint32_t)((spx2 & 7) << 4);
    const uint4* khp = g_kfrag + (b*2 + 0)*1024;
    const uint4* klp = g_kfrag + (b*2 + 1)*1024;

    #pragma unroll
    for (int kc = 0; kc < 4; kc++) {
        const uint32_t kub = (uint32_t)(kc*32 + bkh*16);
        uint4 ah0 = khp[kc*256 + (mgrp*2)*32 + lane];
        uint4 ah1 = khp[kc*256 + (mgrp*2 + 1)*32 + lane];
        uint4 al0 = klp[kc*256 + (mgrp*2)*32 + lane];
        uint4 al1 = klp[kc*256 + (mgrp*2 + 1)*32 + lane];
        uint32_t h0,h1,h2,h3, h4,h5,h6,h7;
        LDSM4(h0,h1,h2,h3, bH1 + (kub ^ bx1));
        LDSM4(h4,h5,h6,h7, bH2 + (kub ^ bx2));
        uint32_t l0,l1,l2,l3, l4,l5,l6,l7;
        LDSM4(l0,l1,l2,l3, bL1 + (kub ^ bx1));
        LDSM4(l4,l5,l6,l7, bL2 + (kub ^ bx2));
        MMA16816(acc[0][0], ah0.x,ah0.y,ah0.z,ah0.w, h0,h1);
        MMA16816(acc[0][1], ah0.x,ah0.y,ah0.z,ah0.w, h2,h3);
        MMA16816(acc[0][2], ah0.x,ah0.y,ah0.z,ah0.w, h4,h5);
        MMA16816(acc[0][3], ah0.x,ah0.y,ah0.z,ah0.w, h6,h7);
        MMA16816(acc[0][0], ah0.x,ah0.y,ah0.z,ah0.w, l0,l1);
        MMA16816(acc[0][1], ah0.x,ah0.y,ah0.z,ah0.w, l2,l3);
        MMA16816(acc[0][2], ah0.x,ah0.y,ah0.z,ah0.w, l4,l5);
        MMA16816(acc[0][3], ah0.x,ah0.y,ah0.z,ah0.w, l6,l7);
        MMA16816(acc[0][0], al0.x,al0.y,al0.z,al0.w, h0,h1);
        MMA16816(acc[0][1], al0.x,al0.y,al0.z,al0.w, h2,h3);
        MMA16816(acc[0][2], al0.x,al0.y,al0.z,al0.w, h4,h5);
        MMA16816(acc[0][3], al0.x,al0.y,al0.z,al0.w, h6,h7);
        MMA16816(acc[1][0], ah1.x,ah1.y,ah1.z,ah1.w, h0,h1);
        MMA16816(acc[1][1], ah1.x,ah1.y,ah1.z,ah1.w, h2,h3);
        MMA16816(acc[1][2], ah1.x,ah1.y,ah1.z,ah1.w, h4,h5);
        MMA16816(acc[1][3], ah1.x,ah1.y,ah1.z,ah1.w, h6,h7);
        MMA16816(acc[1][0], ah1.x,ah1.y,ah1.z,ah1.w, l0,l1);
        MMA16816(acc[1][1], ah1.x,ah1.y,ah1.z,ah1.w, l2,l3);
        MMA16816(acc[1][2], ah1.x,ah1.y,ah1.z,ah1.w, l4,l5);
        MMA16816(acc[1][3], ah1.x,ah1.y,ah1.z,ah1.w, l6,l7);
        MMA16816(acc[1][0], al1.x,al1.y,al1.z,al1.w, h0,h1);
        MMA16816(acc[1][1], al1.x,al1.y,al1.z,al1.w, h2,h3);
        MMA16816(acc[1][2], al1.x,al1.y,al1.z,al1.w, h4,h5);
        MMA16816(acc[1][3], al1.x,al1.y,al1.z,al1.w, h6,h7);
    }
}

// ---- pass 1: stats only (no mask writes) ----
__global__ __launch_bounds__(256)
void bmm_stats_kernel(const float* __restrict__ mf)
{
    extern __shared__ char bsm[];
    const uint32_t sb = smem_u32(bsm);
    float* rs = (float*)(bsm + BM_RS);
    float* rq = (float*)(bsm + BM_RQ);
    const int b = blockIdx.y;
    const int v0 = blockIdx.x * 64;
    const int tid = threadIdx.x;
    const int wid = tid >> 5, lane = tid & 31;

    float acc[2][4][4] = {};
    bmm_core(mf, sb, b, v0, tid, wid, lane, acc);

    // rows >= NN are zero in kfrag -> contribute 0 to both moments
    float psum = 0.f, psq = 0.f;
    #pragma unroll
    for (int mt = 0; mt < 2; mt++)
        #pragma unroll
        for (int j = 0; j < 4; j++)
            #pragma unroll
            for (int e = 0; e < 4; e++) {
                float a = acc[mt][j][e];
                psum += a; psq += a*a;
            }
    rs[tid] = psum; rq[tid] = psq;
    __syncthreads();
    for (int s2 = 128; s2 > 0; s2 >>= 1) {
        if (tid < s2) { rs[tid] += rs[tid+s2]; rq[tid] += rq[tid+s2]; }
        __syncthreads();
    }
    if (tid == 0) {
        atomicAdd(&g_psum, (double)rs[0]);
        atomicAdd(&g_psumsq, (double)rq[0]);
    }
}

// ---- stats finalize ----
__global__ void stats_fin_kernel(const float* __restrict__ gam,
                                 const float* __restrict__ bet)
{
    double mean = g_psum / (double)PM_ELEMS;
    double var = g_psumsq / (double)PM_ELEMS - mean*mean;
    float inv = (float)(1.0 / sqrt(var + (double)EPSV));
    float sc = gam[0] * inv;
    g_scaleS = sc;
    g_shiftS = bet[0] - (float)mean * sc;
}

// ---- pass 2: recompute + write normalized masks ----
__global__ __launch_bounds__(256)
void bmm_write_kernel(const float* __restrict__ mf, float* __restrict__ pm)
{
    extern __shared__ char bsm[];
    const uint32_t sb = smem_u32(bsm);
    float* S = (float*)(bsm + BM_S);
    const int b = blockIdx.y;
    const int v0 = blockIdx.x * 64;
    const int tid = threadIdx.x;
    const int wid = tid >> 5, lane = tid & 31;

    float acc[2][4][4] = {};
    bmm_core(mf, sb, b, v0, tid, wid, lane, acc);

    const int mgrp = wid >> 1;
    const int pxg  = wid & 1;
    #pragma unroll
    for (int mt = 0; mt < 2; mt++) {
        #pragma unroll
        for (int j = 0; j < 4; j++) {
            int pc = pxg*32 + 8*j + 2*(lane & 3);
            int mr = mgrp*32 + mt*16 + (lane >> 2);
            S[mr*65 + pc]           = acc[mt][j][0];
            S[mr*65 + pc + 1]       = acc[mt][j][1];
            S[(mr+8)*65 + pc]       = acc[mt][j][2];
            S[(mr+8)*65 + pc + 1]   = acc[mt][j][3];
        }
    }
    __syncthreads();

    const float sc = g_scaleS, sh = g_shiftS;
    float* po = pm + (size_t)b*NN*VV + v0;
    for (int idx = tid; idx < NN*64; idx += 256) {
        int n = idx >> 6, px = idx & 63;
        po[(size_t)n*VV + px] = S[n*65 + px] * sc + sh;
    }
}

// ---------------- launch ----------------
extern "C" void kernel_launch(void* const* d_in, const int* in_sizes, int n_in,
                              void* d_out, int out_size)
{
    const float* features      = (const float*)d_in[0];
    const float* mask_features = (const float*)d_in[1];
    const float* conv_w        = (const float*)d_in[2];
    const float* conv_b        = (const float*)d_in[3];
    const float* embed         = (const float*)d_in[4];
    const float* mk_w          = (const float*)d_in[5];
    const float* mk_b          = (const float*)d_in[6];
    const float* nk_gamma      = (const float*)d_in[7];
    const float* nk_beta       = (const float*)d_in[8];
    const float* nl_gamma      = (const float*)d_in[9];
    const float* nl_beta       = (const float*)d_in[10];
    const int*   init_masks    = (const int*)d_in[11];
    float* out = (float*)d_out;

    float *bufA = nullptr, *bufB = nullptr;
    uint4 *wfragHi = nullptr, *wfragLo = nullptr;
    cudaGetSymbolAddress((void**)&bufA, g_bufA);
    cudaGetSymbolAddress((void**)&bufB, g_bufB);
    cudaGetSymbolAddress((void**)&wfragHi, g_wfragHi);
    cudaGetSymbolAddress((void**)&wfragLo, g_wfragLo);
    uint16_t* hA = (uint16_t*)bufA;
    uint16_t* hB = (uint16_t*)bufB;

    int full = (out_size >= OUT_FULL) ? 1 : 0;
    int masks_only = (!full && out_size >= PM_ELEMS) ? 1 : 0;

    float* xout  = full ? out : bufB;
    float* ifout = full ? (out + X_ELEMS) : out;
    float* pmout = full ? (out + X_ELEMS + IF_ELEMS) : (masks_only ? out : bufB);
    float* pkout = full ? (out + X_ELEMS + IF_ELEMS + PM_ELEMS) : out;

    static int attr_done = 0;
    if (!attr_done) {
        cudaFuncSetAttribute(conv_mma_kernel,
                             cudaFuncAttributeMaxDynamicSharedMemorySize, CONV_SMEM);
        cudaFuncSetAttribute(bmm_stats_kernel,
                             cudaFuncAttributeMaxDynamicSharedMemorySize, BMM_SMEM);
        cudaFuncSetAttribute(bmm_write_kernel,
                             cudaFuncAttributeMaxDynamicSharedMemorySize, BMM_SMEM);
        attr_done = 1;
    }

    init_zero_kernel<<<1, 256>>>();
    wfrag_kernel<<<72, 256>>>(conv_w);
    trans_kernel<<<2048, 256>>>(features, hB);

    conv_mma_kernel<<<GRIDC, 256, CONV_SMEM>>>(hB, hA,   wfragHi + 0*4608, wfragLo + 0*4608, conv_b + 0,   0);
    conv_mma_kernel<<<GRIDC, 256, CONV_SMEM>>>(hA, hB,   wfragHi + 1*4608, wfragLo + 1*4608, conv_b + 64,  0);
    conv_mma_kernel<<<GRIDC, 256, CONV_SMEM>>>(hB, hA,   wfragHi + 2*4608, wfragLo + 2*4608, conv_b + 128, 0);
    conv_mma_kernel<<<GRIDC, 256, CONV_SMEM>>>(hA, xout, wfragHi + 3*4608, wfragLo + 3*4608, conv_b + 192, 1);

    segsum_kernel<<<dim3(VV/VCH, BB), 256>>>(xout, init_masks);
    instfeat_kernel<<<BB, 256>>>(embed, mk_w, mk_b, ifout, full);
    bnk_kernel<<<1, 256>>>(nk_gamma, nk_beta, pkout, full);

    if (full || masks_only) {
        kfrag_kernel<<<16, 256>>>();
        bmm_stats_kernel<<<dim3(VV/64, BB), 256, BMM_SMEM>>>(mask_features);
        stats_fin_kernel<<<1, 1>>>(nl_gamma, nl_beta);
        bmm_write_kernel<<<dim3(VV/64, BB), 256, BMM_SMEM>>>(mask_features, pmout);
    }
}